// round 1
// baseline (speedup 1.0000x reference)
#include <cuda_runtime.h>
#include <math.h>

#define BB 2
#define SS 2048
#define NH 16
#define DHD 128
#define DRP 64
#define DQK 192
#define DMODEL 2048
#define DC 512
#define DCOMP 768
#define NTOK (BB*SS)

// ---------------- scratch (static device globals; no allocation) ----------------
__device__ float g_kvc [NTOK*DC];        //  8 MB
__device__ float g_kvup[NTOK*DMODEL];    // 32 MB
__device__ float g_qcmp[NTOK*DCOMP];     // 12 MB
__device__ float g_qc  [NTOK*DMODEL];    // 32 MB
__device__ float g_qr  [NTOK*NH*DRP];    // 16 MB
__device__ float g_kr  [NTOK*NH*DRP];    // 16 MB
__device__ float g_attn[NTOK*DMODEL];    // 32 MB

// ---------------- SGEMM: C[M,N] = A[M,K] @ B[K,N] + bias[N] ----------------
// 128x128 block tile, BK=16, 256 threads, 8x8 per thread (split 4+4 halves).
#define GBM 128
#define GBN 128
#define GBK 16
#define LDA_S 132   // padded to kill store bank conflicts

__global__ __launch_bounds__(256) void sgemm_bias(
    const float* __restrict__ A, const float* __restrict__ Bm,
    const float* __restrict__ bias, float* __restrict__ C,
    int M, int N, int K)
{
    __shared__ float As[GBK][LDA_S];   // stored transposed: As[k][m]
    __shared__ float Bs[GBK][GBN];

    const int tid = threadIdx.x;
    const int tx = tid & 15;
    const int ty = tid >> 4;
    const int row0 = blockIdx.y * GBM;
    const int col0 = blockIdx.x * GBN;

    // A tile load mapping: 128 rows x 16 cols = 512 float4; 2 per thread
    const int ar = tid >> 2;          // 0..63
    const int ak = (tid & 3) * 4;     // 0,4,8,12
    // B tile load mapping: 16 rows x 128 cols = 512 float4; 2 per thread
    const int br = tid >> 5;          // 0..7
    const int bc = (tid & 31) * 4;

    float acc[8][8];
    #pragma unroll
    for (int i = 0; i < 8; i++)
        #pragma unroll
        for (int j = 0; j < 8; j++) acc[i][j] = 0.f;

    for (int k0 = 0; k0 < K; k0 += GBK) {
        #pragma unroll
        for (int i2 = 0; i2 < 2; i2++) {
            int r = ar + 64 * i2;
            float4 a = *(const float4*)(A + (size_t)(row0 + r) * K + k0 + ak);
            As[ak + 0][r] = a.x; As[ak + 1][r] = a.y;
            As[ak + 2][r] = a.z; As[ak + 3][r] = a.w;
        }
        #pragma unroll
        for (int i2 = 0; i2 < 2; i2++) {
            int r = br + 8 * i2;
            *(float4*)(&Bs[r][bc]) =
                *(const float4*)(Bm + (size_t)(k0 + r) * N + col0 + bc);
        }
        __syncthreads();

        #pragma unroll
        for (int k = 0; k < GBK; k++) {
            float af[8], bf[8];
            *(float4*)(af)     = *(const float4*)(&As[k][ty * 4]);
            *(float4*)(af + 4) = *(const float4*)(&As[k][64 + ty * 4]);
            *(float4*)(bf)     = *(const float4*)(&Bs[k][tx * 4]);
            *(float4*)(bf + 4) = *(const float4*)(&Bs[k][64 + tx * 4]);
            #pragma unroll
            for (int i = 0; i < 8; i++)
                #pragma unroll
                for (int j = 0; j < 8; j++)
                    acc[i][j] += af[i] * bf[j];
        }
        __syncthreads();
    }

    #pragma unroll
    for (int ib = 0; ib < 2; ib++)
        #pragma unroll
        for (int i = 0; i < 4; i++) {
            int r = row0 + ib * 64 + ty * 4 + i;
            #pragma unroll
            for (int jb = 0; jb < 2; jb++) {
                int c = col0 + jb * 64 + tx * 4;
                float4 o;
                o.x = acc[ib * 4 + i][jb * 4 + 0] + bias[c + 0];
                o.y = acc[ib * 4 + i][jb * 4 + 1] + bias[c + 1];
                o.z = acc[ib * 4 + i][jb * 4 + 2] + bias[c + 2];
                o.w = acc[ib * 4 + i][jb * 4 + 3] + bias[c + 3];
                *(float4*)(C + (size_t)r * N + c) = o;
            }
        }
}

// ---------------- RoPE (in place), layout [tok][head*64 + d] ----------------
__global__ void rope_kernel(float* __restrict__ buf, int n)
{
    int idx = blockIdx.x * blockDim.x + threadIdx.x;
    if (idx >= n) return;
    int i = idx & 31;            // pair index 0..31
    int h = (idx >> 5) & (NH - 1);
    int t = idx >> 9;            // token 0..NTOK-1
    int pos = t & (SS - 1);      // position within sequence

    // inv_freq = 10000^(-2i/64) = 2^(-log2(10000) * i / 32)
    float freq = exp2f(-13.287712379549449f * (float)i / 32.0f);
    float ang = (float)pos * freq;
    float sn, cs;
    sincosf(ang, &sn, &cs);

    float* p = buf + (size_t)t * (NH * DRP) + h * DRP + 2 * i;
    float x1 = p[0], x2 = p[1];
    p[0] = x1 * cs - x2 * sn;
    p[1] = x1 * sn + x2 * cs;
}

// ---------------- fused flash attention (fp32, non-causal) ----------------
// Block: 256 threads = 16x16; tile 64 queries x 64 keys; d_qk=192, d_v=128.
// V = kv_up = first 128 columns of the K tile (no separate V load/storage).
#define FBM 64
#define FBN 64
#define LDQ 196
#define LDK 196
#define LDP 64
#define FLASH_SMEM ((2 * 64 * 196 + 64 * 64) * 4)   // 116736 B

__global__ __launch_bounds__(256) void flash_kernel(
    const float* __restrict__ qc, const float* __restrict__ qr,
    const float* __restrict__ kvup, const float* __restrict__ kr,
    float* __restrict__ out)
{
    extern __shared__ float sm[];
    float* Qs = sm;                  // [64][196]
    float* Ks = sm + 64 * LDQ;       // [64][196] (cols 0..127 double as V)
    float* Ps = Ks + 64 * LDK;       // [64][64]

    const int tid = threadIdx.x;
    const int tx = tid & 15;
    const int ty = tid >> 4;
    const int q0 = blockIdx.x * FBM;
    const int h = blockIdx.y;
    const int b = blockIdx.z;
    const size_t tok0 = (size_t)b * SS;

    // load Q tile: q_c -> cols [0,128), q_r -> cols [128,192)
    for (int idx = tid; idx < 64 * 32; idx += 256) {
        int r = idx >> 5, c4 = (idx & 31) * 4;
        *(float4*)(Qs + r * LDQ + c4) =
            *(const float4*)(qc + (tok0 + q0 + r) * DMODEL + h * DHD + c4);
    }
    for (int idx = tid; idx < 64 * 16; idx += 256) {
        int r = idx >> 4, c4 = (idx & 15) * 4;
        *(float4*)(Qs + r * LDQ + 128 + c4) =
            *(const float4*)(qr + (tok0 + q0 + r) * (NH * DRP) + h * DRP + c4);
    }

    float m_i[4], l_i[4], acc[4][8];
    #pragma unroll
    for (int i = 0; i < 4; i++) {
        m_i[i] = -INFINITY; l_i[i] = 0.f;
        #pragma unroll
        for (int j = 0; j < 8; j++) acc[i][j] = 0.f;
    }
    __syncthreads();

    const float scale = 0.08838834764831845f;  // 1/sqrt(128)

    for (int kt = 0; kt < SS / FBN; kt++) {
        const int k0 = kt * FBN;
        // load K tile (kv_up cols 0..127, k_r cols 128..191)
        for (int idx = tid; idx < 64 * 32; idx += 256) {
            int r = idx >> 5, c4 = (idx & 31) * 4;
            *(float4*)(Ks + r * LDK + c4) =
                *(const float4*)(kvup + (tok0 + k0 + r) * DMODEL + h * DHD + c4);
        }
        for (int idx = tid; idx < 64 * 16; idx += 256) {
            int r = idx >> 4, c4 = (idx & 15) * 4;
            *(float4*)(Ks + r * LDK + 128 + c4) =
                *(const float4*)(kr + (tok0 + k0 + r) * (NH * DRP) + h * DRP + c4);
        }
        __syncthreads();

        // S = Q @ K^T  (rows ty+16i, cols tx+16j)
        float sv[4][4];
        #pragma unroll
        for (int i = 0; i < 4; i++)
            #pragma unroll
            for (int j = 0; j < 4; j++) sv[i][j] = 0.f;

        for (int d = 0; d < DQK; d += 4) {
            float4 qf[4];
            #pragma unroll
            for (int i = 0; i < 4; i++)
                qf[i] = *(const float4*)(Qs + (ty + 16 * i) * LDQ + d);
            #pragma unroll
            for (int j = 0; j < 4; j++) {
                float4 kf = *(const float4*)(Ks + (tx + 16 * j) * LDK + d);
                #pragma unroll
                for (int i = 0; i < 4; i++)
                    sv[i][j] += qf[i].x * kf.x + qf[i].y * kf.y
                              + qf[i].z * kf.z + qf[i].w * kf.w;
            }
        }

        // online softmax (per row, reduced across the 16 tx lanes)
        #pragma unroll
        for (int i = 0; i < 4; i++) {
            float mx = -INFINITY;
            #pragma unroll
            for (int j = 0; j < 4; j++) {
                sv[i][j] *= scale;
                mx = fmaxf(mx, sv[i][j]);
            }
            #pragma unroll
            for (int off = 8; off > 0; off >>= 1)
                mx = fmaxf(mx, __shfl_xor_sync(0xffffffffu, mx, off, 16));
            float m_new = fmaxf(m_i[i], mx);
            float alpha = __expf(m_i[i] - m_new);
            float rs = 0.f;
            #pragma unroll
            for (int j = 0; j < 4; j++) {
                float p = __expf(sv[i][j] - m_new);
                Ps[(ty + 16 * i) * LDP + tx + 16 * j] = p;
                rs += p;
            }
            #pragma unroll
            for (int off = 8; off > 0; off >>= 1)
                rs += __shfl_xor_sync(0xffffffffu, rs, off, 16);
            l_i[i] = l_i[i] * alpha + rs;
            m_i[i] = m_new;
            #pragma unroll
            for (int j = 0; j < 8; j++) acc[i][j] *= alpha;
        }
        __syncwarp();   // Ps rows for this thread are written by its own half-warp

        // acc += P @ V   (V[kk][c] = Ks[kk][c], c < 128)
        for (int kk = 0; kk < FBN; kk += 4) {
            float pa[4][4];
            #pragma unroll
            for (int i = 0; i < 4; i++) {
                float4 t4 = *(const float4*)(Ps + (ty + 16 * i) * LDP + kk);
                pa[i][0] = t4.x; pa[i][1] = t4.y; pa[i][2] = t4.z; pa[i][3] = t4.w;
            }
            #pragma unroll
            for (int k2 = 0; k2 < 4; k2++) {
                const float* vrow = Ks + (kk + k2) * LDK;
                #pragma unroll
                for (int j = 0; j < 8; j++) {
                    float vv = vrow[tx + 16 * j];
                    #pragma unroll
                    for (int i = 0; i < 4; i++)
                        acc[i][j] += pa[i][k2] * vv;
                }
            }
        }
        __syncthreads();  // before next tile overwrites Ks/Ps
    }

    // epilogue: out[b, q, h, c] = acc / l
    #pragma unroll
    for (int i = 0; i < 4; i++) {
        float inv = 1.0f / l_i[i];
        size_t row = (tok0 + q0 + ty + 16 * i) * DMODEL + h * DHD;
        #pragma unroll
        for (int j = 0; j < 8; j++)
            out[row + tx + 16 * j] = acc[i][j] * inv;
    }
}

// ---------------- host launch ----------------
static inline void launch_gemm(const float* A, const float* Bm, const float* bias,
                               float* C, int M, int N, int K)
{
    dim3 grid(N / GBN, M / GBM);
    sgemm_bias<<<grid, 256>>>(A, Bm, bias, C, M, N, K);
}

extern "C" void kernel_launch(void* const* d_in, const int* in_sizes, int n_in,
                              void* d_out, int out_size)
{
    (void)in_sizes; (void)n_in; (void)out_size;
    const float* x   = (const float*)d_in[0];
    const float* Wd  = (const float*)d_in[1];
    const float* bd  = (const float*)d_in[2];
    const float* Wu  = (const float*)d_in[3];
    const float* bu  = (const float*)d_in[4];
    const float* Wqd = (const float*)d_in[5];
    const float* bqd = (const float*)d_in[6];
    const float* Wqu = (const float*)d_in[7];
    const float* bqu = (const float*)d_in[8];
    const float* Wqr = (const float*)d_in[9];
    const float* bqr = (const float*)d_in[10];
    const float* Wkr = (const float*)d_in[11];
    const float* bkr = (const float*)d_in[12];
    const float* Wo  = (const float*)d_in[13];
    const float* bo  = (const float*)d_in[14];
    float* out = (float*)d_out;

    float *kvc, *kvup, *qcmp, *qcb, *qrb, *krb, *attn;
    cudaGetSymbolAddress((void**)&kvc,  g_kvc);
    cudaGetSymbolAddress((void**)&kvup, g_kvup);
    cudaGetSymbolAddress((void**)&qcmp, g_qcmp);
    cudaGetSymbolAddress((void**)&qcb,  g_qc);
    cudaGetSymbolAddress((void**)&qrb,  g_qr);
    cudaGetSymbolAddress((void**)&krb,  g_kr);
    cudaGetSymbolAddress((void**)&attn, g_attn);

    // projections
    launch_gemm(x,    Wd,  bd,  kvc,  NTOK, DC,      DMODEL);   // kv_c
    launch_gemm(kvc,  Wu,  bu,  kvup, NTOK, DMODEL,  DC);       // kv_up
    launch_gemm(x,    Wqd, bqd, qcmp, NTOK, DCOMP,   DMODEL);   // q_cmp
    launch_gemm(qcmp, Wqu, bqu, qcb,  NTOK, DMODEL,  DCOMP);    // q_c
    launch_gemm(qcmp, Wqr, bqr, qrb,  NTOK, NH*DRP,  DCOMP);    // q_r (pre-rope)
    launch_gemm(x,    Wkr, bkr, krb,  NTOK, NH*DRP,  DMODEL);   // k_r (pre-rope)

    // rope
    {
        int n = NTOK * NH * 32;
        int blocks = (n + 255) / 256;
        rope_kernel<<<blocks, 256>>>(qrb, n);
        rope_kernel<<<blocks, 256>>>(krb, n);
    }

    // attention
    cudaFuncSetAttribute(flash_kernel, cudaFuncAttributeMaxDynamicSharedMemorySize,
                         FLASH_SMEM);
    {
        dim3 grid(SS / FBM, NH, BB);
        flash_kernel<<<grid, 256, FLASH_SMEM>>>(qcb, qrb, kvup, krb, attn);
    }

    // output projection
    launch_gemm(attn, Wo, bo, out, NTOK, DMODEL, DMODEL);
}

// round 3
// speedup vs baseline: 1.3647x; 1.3647x over previous
#include <cuda_runtime.h>
#include <math.h>
#include <stdint.h>

#define BB 2
#define SS 2048
#define NH 16
#define DHD 128
#define DRP 64
#define DQK 192
#define DMODEL 2048
#define DC 512
#define DCOMP 768
#define NTOK (BB*SS)

// ---------------- scratch (static device globals; no allocation) ----------------
__device__ float g_kvc [NTOK*DC];
__device__ float g_kvup[NTOK*DMODEL];
__device__ float g_qcmp[NTOK*DCOMP];
__device__ float g_qc  [NTOK*DMODEL];
__device__ float g_qr  [NTOK*NH*DRP];
__device__ float g_kr  [NTOK*NH*DRP];
__device__ float g_attn[NTOK*DMODEL];
// transposed weights (Bt[n][k] = W[k][n])
__device__ float g_wdT [DC*DMODEL];
__device__ float g_wuT [DMODEL*DC];
__device__ float g_wqdT[DCOMP*DMODEL];
__device__ float g_wquT[DMODEL*DCOMP];
__device__ float g_wqrT[(NH*DRP)*DCOMP];
__device__ float g_wkrT[(NH*DRP)*DMODEL];
__device__ float g_woT [DMODEL*DMODEL];

// ================= weight transpose: out[n][k] = in[k][n] =================
__global__ void transpose32(const float* __restrict__ in, float* __restrict__ out,
                            int K, int N)
{
    __shared__ float t[32][33];
    int n0 = blockIdx.x * 32, k0 = blockIdx.y * 32;
    int tx = threadIdx.x, ty = threadIdx.y;  // (32, 8)
    #pragma unroll
    for (int i = 0; i < 4; ++i)
        t[ty + 8*i][tx] = in[(size_t)(k0 + ty + 8*i) * N + n0 + tx];
    __syncthreads();
    #pragma unroll
    for (int i = 0; i < 4; ++i)
        out[(size_t)(n0 + ty + 8*i) * K + k0 + tx] = t[tx][ty + 8*i];
}

// ================= tf32 mma.sync GEMM: C[M,N] = A[M,K] @ Bt[N,K]^T + bias =================
// 128x128 CTA tile, BK=32, 256 threads = 8 warps (2x4), warp tile 64x32.
#define BM 128
#define BN 128
#define BK 32
#define LDS_K 36     // row stride in floats; 36 mod 32 = 4 -> conflict-free frags

__device__ __forceinline__ uint32_t f2tf32(float x) {
    uint32_t r;
    asm("cvt.rna.tf32.f32 %0, %1;" : "=r"(r) : "f"(x));
    return r;
}

__global__ __launch_bounds__(256) void gemm_mma(
    const float* __restrict__ A, const float* __restrict__ Bt,
    const float* __restrict__ bias, float* __restrict__ C,
    int M, int N, int K)
{
    __shared__ uint32_t As[BM * LDS_K];
    __shared__ uint32_t Bs[BN * LDS_K];

    const int tid  = threadIdx.x;
    const int wid  = tid >> 5;
    const int lane = tid & 31;
    const int wm = wid >> 2;          // 0..1
    const int wn = wid & 3;           // 0..3
    const int gr = lane >> 2;         // 0..7
    const int gc = lane & 3;          // 0..3
    const int wr = wm * 64;
    const int wc = wn * 32;

    const int row0 = blockIdx.y * BM;
    const int col0 = blockIdx.x * BN;

    const float* Ag = A  + (size_t)row0 * K;
    const float* Bg = Bt + (size_t)col0 * K;

    // global load mapping: 128 rows x 8 float4 per tile; thread -> rows lr+32i, col lk
    const int lr = tid >> 3;          // 0..31
    const int lk = (tid & 7) * 4;     // 0,4,...,28

    float acc[4][4][4];
    #pragma unroll
    for (int i = 0; i < 4; ++i)
        #pragma unroll
        for (int j = 0; j < 4; ++j)
            #pragma unroll
            for (int c = 0; c < 4; ++c) acc[i][j][c] = 0.f;

    float4 pa[4], pb[4];
    #pragma unroll
    for (int i = 0; i < 4; ++i) {
        pa[i] = *(const float4*)(Ag + (size_t)(lr + 32*i) * K + lk);
        pb[i] = *(const float4*)(Bg + (size_t)(lr + 32*i) * K + lk);
    }

    const int niter = K / BK;
    for (int it = 0; it < niter; ++it) {
        // store prefetched tile to smem (with tf32 rounding)
        #pragma unroll
        for (int i = 0; i < 4; ++i) {
            int r = lr + 32*i;
            uint32_t* pA = &As[r * LDS_K + lk];
            pA[0] = f2tf32(pa[i].x); pA[1] = f2tf32(pa[i].y);
            pA[2] = f2tf32(pa[i].z); pA[3] = f2tf32(pa[i].w);
            uint32_t* pB = &Bs[r * LDS_K + lk];
            pB[0] = f2tf32(pb[i].x); pB[1] = f2tf32(pb[i].y);
            pB[2] = f2tf32(pb[i].z); pB[3] = f2tf32(pb[i].w);
        }
        __syncthreads();

        // prefetch next tile (overlaps with MMA below)
        if (it + 1 < niter) {
            const float* An = Ag + (size_t)(it + 1) * BK;
            const float* Bn = Bg + (size_t)(it + 1) * BK;
            #pragma unroll
            for (int i = 0; i < 4; ++i) {
                pa[i] = *(const float4*)(An + (size_t)(lr + 32*i) * K + lk);
                pb[i] = *(const float4*)(Bn + (size_t)(lr + 32*i) * K + lk);
            }
        }

        // compute: 4 k-steps of 8
        #pragma unroll
        for (int ks = 0; ks < 4; ++ks) {
            const int k0 = ks * 8;
            uint32_t a0[4], a1[4], a2[4], a3[4];
            uint32_t b0[4], b1[4];
            #pragma unroll
            for (int i = 0; i < 4; ++i) {
                const uint32_t* base = &As[(wr + 16*i + gr) * LDS_K + k0 + gc];
                a0[i] = base[0];
                a2[i] = base[4];
                a1[i] = base[8 * LDS_K];
                a3[i] = base[8 * LDS_K + 4];
            }
            #pragma unroll
            for (int j = 0; j < 4; ++j) {
                const uint32_t* base = &Bs[(wc + 8*j + gr) * LDS_K + k0 + gc];
                b0[j] = base[0];
                b1[j] = base[4];
            }
            #pragma unroll
            for (int i = 0; i < 4; ++i)
                #pragma unroll
                for (int j = 0; j < 4; ++j) {
                    asm volatile(
                        "mma.sync.aligned.m16n8k8.row.col.f32.tf32.tf32.f32 "
                        "{%0,%1,%2,%3}, {%4,%5,%6,%7}, {%8,%9}, {%0,%1,%2,%3};"
                        : "+f"(acc[i][j][0]), "+f"(acc[i][j][1]),
                          "+f"(acc[i][j][2]), "+f"(acc[i][j][3])
                        : "r"(a0[i]), "r"(a1[i]), "r"(a2[i]), "r"(a3[i]),
                          "r"(b0[j]), "r"(b1[j]));
                }
        }
        __syncthreads();
    }

    // epilogue: c0,c1 -> (row gr, cols 2gc,2gc+1); c2,c3 -> row gr+8
    #pragma unroll
    for (int j = 0; j < 4; ++j) {
        int c = col0 + wc + 8*j + 2*gc;
        float bv0 = bias[c], bv1 = bias[c + 1];
        #pragma unroll
        for (int i = 0; i < 4; ++i) {
            int r = row0 + wr + 16*i + gr;
            float2 v0 = make_float2(acc[i][j][0] + bv0, acc[i][j][1] + bv1);
            float2 v1 = make_float2(acc[i][j][2] + bv0, acc[i][j][3] + bv1);
            *(float2*)(C + (size_t)r * N + c) = v0;
            *(float2*)(C + (size_t)(r + 8) * N + c) = v1;
        }
    }
}

// ================= RoPE (in place), layout [tok][head*64 + d] =================
__global__ void rope_kernel(float* __restrict__ buf, int n)
{
    int idx = blockIdx.x * blockDim.x + threadIdx.x;
    if (idx >= n) return;
    int i = idx & 31;
    int h = (idx >> 5) & (NH - 1);
    int t = idx >> 9;
    int pos = t & (SS - 1);

    float freq = exp2f(-13.287712379549449f * (float)i / 32.0f);
    float ang = (float)pos * freq;
    float sn, cs;
    sincosf(ang, &sn, &cs);

    float* p = buf + (size_t)t * (NH * DRP) + h * DRP + 2 * i;
    float x1 = p[0], x2 = p[1];
    p[0] = x1 * cs - x2 * sn;
    p[1] = x1 * sn + x2 * cs;
}

// ================= fused flash attention (fp32, non-causal) =================
#define FBM 64
#define FBN 64
#define LDQ 196
#define LDK 196
#define LDP 64
#define FLASH_SMEM ((2 * 64 * 196 + 64 * 64) * 4)

__global__ __launch_bounds__(256) void flash_kernel(
    const float* __restrict__ qc, const float* __restrict__ qr,
    const float* __restrict__ kvup, const float* __restrict__ kr,
    float* __restrict__ out)
{
    extern __shared__ float sm[];
    float* Qs = sm;
    float* Ks = sm + 64 * LDQ;
    float* Ps = Ks + 64 * LDK;

    const int tid = threadIdx.x;
    const int tx = tid & 15;
    const int ty = tid >> 4;
    const int q0 = blockIdx.x * FBM;
    const int h = blockIdx.y;
    const int b = blockIdx.z;
    const size_t tok0 = (size_t)b * SS;

    for (int idx = tid; idx < 64 * 32; idx += 256) {
        int r = idx >> 5, c4 = (idx & 31) * 4;
        *(float4*)(Qs + r * LDQ + c4) =
            *(const float4*)(qc + (tok0 + q0 + r) * DMODEL + h * DHD + c4);
    }
    for (int idx = tid; idx < 64 * 16; idx += 256) {
        int r = idx >> 4, c4 = (idx & 15) * 4;
        *(float4*)(Qs + r * LDQ + 128 + c4) =
            *(const float4*)(qr + (tok0 + q0 + r) * (NH * DRP) + h * DRP + c4);
    }

    float m_i[4], l_i[4], acc[4][8];
    #pragma unroll
    for (int i = 0; i < 4; i++) {
        m_i[i] = -INFINITY; l_i[i] = 0.f;
        #pragma unroll
        for (int j = 0; j < 8; j++) acc[i][j] = 0.f;
    }
    __syncthreads();

    const float scale = 0.08838834764831845f;

    for (int kt = 0; kt < SS / FBN; kt++) {
        const int k0 = kt * FBN;
        for (int idx = tid; idx < 64 * 32; idx += 256) {
            int r = idx >> 5, c4 = (idx & 31) * 4;
            *(float4*)(Ks + r * LDK + c4) =
                *(const float4*)(kvup + (tok0 + k0 + r) * DMODEL + h * DHD + c4);
        }
        for (int idx = tid; idx < 64 * 16; idx += 256) {
            int r = idx >> 4, c4 = (idx & 15) * 4;
            *(float4*)(Ks + r * LDK + 128 + c4) =
                *(const float4*)(kr + (tok0 + k0 + r) * (NH * DRP) + h * DRP + c4);
        }
        __syncthreads();

        float sv[4][4];
        #pragma unroll
        for (int i = 0; i < 4; i++)
            #pragma unroll
            for (int j = 0; j < 4; j++) sv[i][j] = 0.f;

        for (int d = 0; d < DQK; d += 4) {
            float4 qf[4];
            #pragma unroll
            for (int i = 0; i < 4; i++)
                qf[i] = *(const float4*)(Qs + (ty + 16 * i) * LDQ + d);
            #pragma unroll
            for (int j = 0; j < 4; j++) {
                float4 kf = *(const float4*)(Ks + (tx + 16 * j) * LDK + d);
                #pragma unroll
                for (int i = 0; i < 4; i++)
                    sv[i][j] += qf[i].x * kf.x + qf[i].y * kf.y
                              + qf[i].z * kf.z + qf[i].w * kf.w;
            }
        }

        #pragma unroll
        for (int i = 0; i < 4; i++) {
            float mx = -INFINITY;
            #pragma unroll
            for (int j = 0; j < 4; j++) {
                sv[i][j] *= scale;
                mx = fmaxf(mx, sv[i][j]);
            }
            #pragma unroll
            for (int off = 8; off > 0; off >>= 1)
                mx = fmaxf(mx, __shfl_xor_sync(0xffffffffu, mx, off, 16));
            float m_new = fmaxf(m_i[i], mx);
            float alpha = __expf(m_i[i] - m_new);
            float rs = 0.f;
            #pragma unroll
            for (int j = 0; j < 4; j++) {
                float p = __expf(sv[i][j] - m_new);
                Ps[(ty + 16 * i) * LDP + tx + 16 * j] = p;
                rs += p;
            }
            #pragma unroll
            for (int off = 8; off > 0; off >>= 1)
                rs += __shfl_xor_sync(0xffffffffu, rs, off, 16);
            l_i[i] = l_i[i] * alpha + rs;
            m_i[i] = m_new;
            #pragma unroll
            for (int j = 0; j < 8; j++) acc[i][j] *= alpha;
        }
        __syncwarp();

        for (int kk = 0; kk < FBN; kk += 4) {
            float pa[4][4];
            #pragma unroll
            for (int i = 0; i < 4; i++) {
                float4 t4 = *(const float4*)(Ps + (ty + 16 * i) * LDP + kk);
                pa[i][0] = t4.x; pa[i][1] = t4.y; pa[i][2] = t4.z; pa[i][3] = t4.w;
            }
            #pragma unroll
            for (int k2 = 0; k2 < 4; k2++) {
                const float* vrow = Ks + (kk + k2) * LDK;
                #pragma unroll
                for (int j = 0; j < 8; j++) {
                    float vv = vrow[tx + 16 * j];
                    #pragma unroll
                    for (int i = 0; i < 4; i++)
                        acc[i][j] += pa[i][k2] * vv;
                }
            }
        }
        __syncthreads();
    }

    #pragma unroll
    for (int i = 0; i < 4; i++) {
        float inv = 1.0f / l_i[i];
        size_t row = (tok0 + q0 + ty + 16 * i) * DMODEL + h * DHD;
        #pragma unroll
        for (int j = 0; j < 8; j++)
            out[row + tx + 16 * j] = acc[i][j] * inv;
    }
}

// ================= host launch =================
static inline void launch_gemm_mma(const float* A, const float* Bt, const float* bias,
                                   float* C, int M, int N, int K)
{
    dim3 grid(N / BN, M / BM);
    gemm_mma<<<grid, 256>>>(A, Bt, bias, C, M, N, K);
}
static inline void launch_transpose(const float* in, float* out, int K, int N)
{
    transpose32<<<dim3(N / 32, K / 32), dim3(32, 8)>>>(in, out, K, N);
}

extern "C" void kernel_launch(void* const* d_in, const int* in_sizes, int n_in,
                              void* d_out, int out_size)
{
    (void)in_sizes; (void)n_in; (void)out_size;
    const float* x   = (const float*)d_in[0];
    const float* Wd  = (const float*)d_in[1];
    const float* bd  = (const float*)d_in[2];
    const float* Wu  = (const float*)d_in[3];
    const float* bu  = (const float*)d_in[4];
    const float* Wqd = (const float*)d_in[5];
    const float* bqd = (const float*)d_in[6];
    const float* Wqu = (const float*)d_in[7];
    const float* bqu = (const float*)d_in[8];
    const float* Wqr = (const float*)d_in[9];
    const float* bqr = (const float*)d_in[10];
    const float* Wkr = (const float*)d_in[11];
    const float* bkr = (const float*)d_in[12];
    const float* Wo  = (const float*)d_in[13];
    const float* bo  = (const float*)d_in[14];
    float* out = (float*)d_out;

    float *kvc, *kvup, *qcmp, *qcb, *qrb, *krb, *attn;
    float *wdT, *wuT, *wqdT, *wquT, *wqrT, *wkrT, *woT;
    cudaGetSymbolAddress((void**)&kvc,  g_kvc);
    cudaGetSymbolAddress((void**)&kvup, g_kvup);
    cudaGetSymbolAddress((void**)&qcmp, g_qcmp);
    cudaGetSymbolAddress((void**)&qcb,  g_qc);
    cudaGetSymbolAddress((void**)&qrb,  g_qr);
    cudaGetSymbolAddress((void**)&krb,  g_kr);
    cudaGetSymbolAddress((void**)&attn, g_attn);
    cudaGetSymbolAddress((void**)&wdT,  g_wdT);
    cudaGetSymbolAddress((void**)&wuT,  g_wuT);
    cudaGetSymbolAddress((void**)&wqdT, g_wqdT);
    cudaGetSymbolAddress((void**)&wquT, g_wquT);
    cudaGetSymbolAddress((void**)&wqrT, g_wqrT);
    cudaGetSymbolAddress((void**)&wkrT, g_wkrT);
    cudaGetSymbolAddress((void**)&woT,  g_woT);

    cudaFuncSetAttribute(flash_kernel, cudaFuncAttributeMaxDynamicSharedMemorySize,
                         FLASH_SMEM);

    // weight transposes (K-major B for mma row.col)
    launch_transpose(Wd,  wdT,  DMODEL, DC);
    launch_transpose(Wu,  wuT,  DC,     DMODEL);
    launch_transpose(Wqd, wqdT, DMODEL, DCOMP);
    launch_transpose(Wqu, wquT, DCOMP,  DMODEL);
    launch_transpose(Wqr, wqrT, DCOMP,  NH*DRP);
    launch_transpose(Wkr, wkrT, DMODEL, NH*DRP);
    launch_transpose(Wo,  woT,  DMODEL, DMODEL);

    // projections (tf32 mma.sync)
    launch_gemm_mma(x,    wdT,  bd,  kvc,  NTOK, DC,     DMODEL);
    launch_gemm_mma(kvc,  wuT,  bu,  kvup, NTOK, DMODEL, DC);
    launch_gemm_mma(x,    wqdT, bqd, qcmp, NTOK, DCOMP,  DMODEL);
    launch_gemm_mma(qcmp, wquT, bqu, qcb,  NTOK, DMODEL, DCOMP);
    launch_gemm_mma(qcmp, wqrT, bqr, qrb,  NTOK, NH*DRP, DCOMP);
    launch_gemm_mma(x,    wkrT, bkr, krb,  NTOK, NH*DRP, DMODEL);

    // rope
    {
        int n = NTOK * NH * 32;
        int blocks = (n + 255) / 256;
        rope_kernel<<<blocks, 256>>>(qrb, n);
        rope_kernel<<<blocks, 256>>>(krb, n);
    }

    // attention (fp32 flash)
    {
        dim3 grid(SS / FBM, NH, BB);
        flash_kernel<<<grid, 256, FLASH_SMEM>>>(qcb, qrb, kvup, krb, attn);
    }

    // output projection
    launch_gemm_mma(attn, woT, bo, out, NTOK, DMODEL, DMODEL);
}

// round 4
// speedup vs baseline: 2.7581x; 2.0210x over previous
#include <cuda_runtime.h>
#include <math.h>
#include <stdint.h>

#define BB 2
#define SS 2048
#define NH 16
#define DHD 128
#define DRP 64
#define DQK 192
#define DMODEL 2048
#define DC 512
#define DCOMP 768
#define NTOK (BB*SS)

// ---------------- scratch (static device globals; no allocation) ----------------
__device__ float g_kvc [NTOK*DC];
__device__ float g_kvup[NTOK*DMODEL];
__device__ float g_qcmp[NTOK*DCOMP];
__device__ float g_qc  [NTOK*DMODEL];
__device__ float g_qr  [NTOK*NH*DRP];
__device__ float g_kr  [NTOK*NH*DRP];
__device__ float g_attn[NTOK*DMODEL];
// transposed weights (Bt[n][k] = W[k][n])
__device__ float g_wdT [DC*DMODEL];
__device__ float g_wuT [DMODEL*DC];
__device__ float g_wqdT[DCOMP*DMODEL];
__device__ float g_wquT[DMODEL*DCOMP];
__device__ float g_wqrT[(NH*DRP)*DCOMP];
__device__ float g_wkrT[(NH*DRP)*DMODEL];
__device__ float g_woT [DMODEL*DMODEL];

__device__ __forceinline__ uint32_t f2tf32(float x) {
    uint32_t r;
    asm("cvt.rna.tf32.f32 %0, %1;" : "=r"(r) : "f"(x));
    return r;
}

#define MMA_TF32(d0,d1,d2,d3, a0,a1,a2,a3, b0,b1) \
    asm volatile( \
        "mma.sync.aligned.m16n8k8.row.col.f32.tf32.tf32.f32 " \
        "{%0,%1,%2,%3}, {%4,%5,%6,%7}, {%8,%9}, {%0,%1,%2,%3};" \
        : "+f"(d0), "+f"(d1), "+f"(d2), "+f"(d3) \
        : "r"(a0), "r"(a1), "r"(a2), "r"(a3), "r"(b0), "r"(b1))

// ================= weight transpose: out[n][k] = in[k][n] =================
__global__ void transpose32(const float* __restrict__ in, float* __restrict__ out,
                            int K, int N)
{
    __shared__ float t[32][33];
    int n0 = blockIdx.x * 32, k0 = blockIdx.y * 32;
    int tx = threadIdx.x, ty = threadIdx.y;  // (32, 8)
    #pragma unroll
    for (int i = 0; i < 4; ++i)
        t[ty + 8*i][tx] = in[(size_t)(k0 + ty + 8*i) * N + n0 + tx];
    __syncthreads();
    #pragma unroll
    for (int i = 0; i < 4; ++i)
        out[(size_t)(n0 + ty + 8*i) * K + k0 + tx] = t[tx][ty + 8*i];
}

// ================= tf32 mma.sync GEMM: C[M,N] = A[M,K] @ Bt[N,K]^T + bias =================
#define BM 128
#define BN 128
#define BK 32
#define LDS_K 36

__global__ __launch_bounds__(256) void gemm_mma(
    const float* __restrict__ A, const float* __restrict__ Bt,
    const float* __restrict__ bias, float* __restrict__ C,
    int M, int N, int K)
{
    __shared__ uint32_t As[BM * LDS_K];
    __shared__ uint32_t Bs[BN * LDS_K];

    const int tid  = threadIdx.x;
    const int wid  = tid >> 5;
    const int lane = tid & 31;
    const int wm = wid >> 2;
    const int wn = wid & 3;
    const int gr = lane >> 2;
    const int gc = lane & 3;
    const int wr = wm * 64;
    const int wc = wn * 32;

    const int row0 = blockIdx.y * BM;
    const int col0 = blockIdx.x * BN;

    const float* Ag = A  + (size_t)row0 * K;
    const float* Bg = Bt + (size_t)col0 * K;

    const int lr = tid >> 3;
    const int lk = (tid & 7) * 4;

    float acc[4][4][4];
    #pragma unroll
    for (int i = 0; i < 4; ++i)
        #pragma unroll
        for (int j = 0; j < 4; ++j)
            #pragma unroll
            for (int c = 0; c < 4; ++c) acc[i][j][c] = 0.f;

    float4 pa[4], pb[4];
    #pragma unroll
    for (int i = 0; i < 4; ++i) {
        pa[i] = *(const float4*)(Ag + (size_t)(lr + 32*i) * K + lk);
        pb[i] = *(const float4*)(Bg + (size_t)(lr + 32*i) * K + lk);
    }

    const int niter = K / BK;
    for (int it = 0; it < niter; ++it) {
        #pragma unroll
        for (int i = 0; i < 4; ++i) {
            int r = lr + 32*i;
            uint32_t* pA = &As[r * LDS_K + lk];
            pA[0] = f2tf32(pa[i].x); pA[1] = f2tf32(pa[i].y);
            pA[2] = f2tf32(pa[i].z); pA[3] = f2tf32(pa[i].w);
            uint32_t* pB = &Bs[r * LDS_K + lk];
            pB[0] = f2tf32(pb[i].x); pB[1] = f2tf32(pb[i].y);
            pB[2] = f2tf32(pb[i].z); pB[3] = f2tf32(pb[i].w);
        }
        __syncthreads();

        if (it + 1 < niter) {
            const float* An = Ag + (size_t)(it + 1) * BK;
            const float* Bn = Bg + (size_t)(it + 1) * BK;
            #pragma unroll
            for (int i = 0; i < 4; ++i) {
                pa[i] = *(const float4*)(An + (size_t)(lr + 32*i) * K + lk);
                pb[i] = *(const float4*)(Bn + (size_t)(lr + 32*i) * K + lk);
            }
        }

        #pragma unroll
        for (int ks = 0; ks < 4; ++ks) {
            const int k0 = ks * 8;
            uint32_t a0[4], a1[4], a2[4], a3[4];
            uint32_t b0[4], b1[4];
            #pragma unroll
            for (int i = 0; i < 4; ++i) {
                const uint32_t* base = &As[(wr + 16*i + gr) * LDS_K + k0 + gc];
                a0[i] = base[0];
                a2[i] = base[4];
                a1[i] = base[8 * LDS_K];
                a3[i] = base[8 * LDS_K + 4];
            }
            #pragma unroll
            for (int j = 0; j < 4; ++j) {
                const uint32_t* base = &Bs[(wc + 8*j + gr) * LDS_K + k0 + gc];
                b0[j] = base[0];
                b1[j] = base[4];
            }
            #pragma unroll
            for (int i = 0; i < 4; ++i)
                #pragma unroll
                for (int j = 0; j < 4; ++j)
                    MMA_TF32(acc[i][j][0], acc[i][j][1], acc[i][j][2], acc[i][j][3],
                             a0[i], a1[i], a2[i], a3[i], b0[j], b1[j]);
        }
        __syncthreads();
    }

    #pragma unroll
    for (int j = 0; j < 4; ++j) {
        int c = col0 + wc + 8*j + 2*gc;
        float bv0 = bias[c], bv1 = bias[c + 1];
        #pragma unroll
        for (int i = 0; i < 4; ++i) {
            int r = row0 + wr + 16*i + gr;
            float2 v0 = make_float2(acc[i][j][0] + bv0, acc[i][j][1] + bv1);
            float2 v1 = make_float2(acc[i][j][2] + bv0, acc[i][j][3] + bv1);
            *(float2*)(C + (size_t)r * N + c) = v0;
            *(float2*)(C + (size_t)(r + 8) * N + c) = v1;
        }
    }
}

// ================= RoPE (in place), layout [tok][head*64 + d] =================
__global__ void rope_kernel(float* __restrict__ buf, int n)
{
    int idx = blockIdx.x * blockDim.x + threadIdx.x;
    if (idx >= n) return;
    int i = idx & 31;
    int h = (idx >> 5) & (NH - 1);
    int t = idx >> 9;
    int pos = t & (SS - 1);

    float freq = exp2f(-13.287712379549449f * (float)i / 32.0f);
    float ang = (float)pos * freq;
    float sn, cs;
    sincosf(ang, &sn, &cs);

    float* p = buf + (size_t)t * (NH * DRP) + h * DRP + 2 * i;
    float x1 = p[0], x2 = p[1];
    p[0] = x1 * cs - x2 * sn;
    p[1] = x1 * sn + x2 * cs;
}

// ================= flash attention with tf32 mma.sync =================
// CTA: 256 threads = 8 warps; 128 queries per CTA (16 per warp); 64-key tiles.
// Q,K in smem as tf32 (stride 196); V aliases first 128 cols of K tile.
#define ALDQ 196
#define ALDP 68
#define FL_SMEM ((128*ALDQ + 64*ALDQ + 128*ALDP) * 4)   // 185,344 B

__global__ __launch_bounds__(256, 1) void flash_mma(
    const float* __restrict__ qc, const float* __restrict__ qr,
    const float* __restrict__ kvup, const float* __restrict__ kr,
    float* __restrict__ out)
{
    extern __shared__ uint32_t sm[];
    uint32_t* Qs = sm;                       // [128][196]
    uint32_t* Ks = sm + 128 * ALDQ;          // [64][196]
    uint32_t* Ps = Ks + 64 * ALDQ;           // [128][68]

    const int tid  = threadIdx.x;
    const int wid  = tid >> 5;
    const int lane = tid & 31;
    const int gr = lane >> 2;        // 0..7
    const int gc = lane & 3;         // 0..3
    const int wq = wid * 16;         // warp's query offset in tile

    const int q0 = blockIdx.x * 128;
    const int h  = blockIdx.y;
    const int b  = blockIdx.z;
    const size_t tok0 = (size_t)b * SS;

    // ---- load Q tile (tf32): q_c cols [0,128), q_r cols [128,192) ----
    for (int idx = tid; idx < 128 * 32; idx += 256) {
        int r = idx >> 5, c4 = (idx & 31) * 4;
        float4 v = *(const float4*)(qc + (tok0 + q0 + r) * DMODEL + h * DHD + c4);
        uint32_t* p = Qs + r * ALDQ + c4;
        p[0] = f2tf32(v.x); p[1] = f2tf32(v.y); p[2] = f2tf32(v.z); p[3] = f2tf32(v.w);
    }
    for (int idx = tid; idx < 128 * 16; idx += 256) {
        int r = idx >> 4, c4 = (idx & 15) * 4;
        float4 v = *(const float4*)(qr + (tok0 + q0 + r) * (NH * DRP) + h * DRP + c4);
        uint32_t* p = Qs + r * ALDQ + 128 + c4;
        p[0] = f2tf32(v.x); p[1] = f2tf32(v.y); p[2] = f2tf32(v.z); p[3] = f2tf32(v.w);
    }

    float m0 = -INFINITY, m1 = -INFINITY, l0 = 0.f, l1 = 0.f;
    float o[16][4];
    #pragma unroll
    for (int j = 0; j < 16; ++j)
        #pragma unroll
        for (int c = 0; c < 4; ++c) o[j][c] = 0.f;

    const float scale = 0.08838834764831845f;  // 1/sqrt(128)

    for (int kt = 0; kt < SS / 64; ++kt) {
        const int k0tok = kt * 64;
        __syncthreads();   // previous iteration's Ks reads done
        for (int idx = tid; idx < 64 * 32; idx += 256) {
            int r = idx >> 5, c4 = (idx & 31) * 4;
            float4 v = *(const float4*)(kvup + (tok0 + k0tok + r) * DMODEL + h * DHD + c4);
            uint32_t* p = Ks + r * ALDQ + c4;
            p[0] = f2tf32(v.x); p[1] = f2tf32(v.y); p[2] = f2tf32(v.z); p[3] = f2tf32(v.w);
        }
        for (int idx = tid; idx < 64 * 16; idx += 256) {
            int r = idx >> 4, c4 = (idx & 15) * 4;
            float4 v = *(const float4*)(kr + (tok0 + k0tok + r) * (NH * DRP) + h * DRP + c4);
            uint32_t* p = Ks + r * ALDQ + 128 + c4;
            p[0] = f2tf32(v.x); p[1] = f2tf32(v.y); p[2] = f2tf32(v.z); p[3] = f2tf32(v.w);
        }
        __syncthreads();

        // ---- S = Q @ K^T : per-warp 16x64, 24 ksteps x 8 n-atoms ----
        float s[8][4];
        #pragma unroll
        for (int j = 0; j < 8; ++j)
            #pragma unroll
            for (int c = 0; c < 4; ++c) s[j][c] = 0.f;

        #pragma unroll 4
        for (int ks = 0; ks < 24; ++ks) {
            const int k0 = ks * 8;
            const uint32_t* abase = Qs + (wq + gr) * ALDQ + k0 + gc;
            uint32_t a0 = abase[0];
            uint32_t a2 = abase[4];
            uint32_t a1 = abase[8 * ALDQ];
            uint32_t a3 = abase[8 * ALDQ + 4];
            #pragma unroll
            for (int j = 0; j < 8; ++j) {
                const uint32_t* bbase = Ks + (8*j + gr) * ALDQ + k0 + gc;
                uint32_t b0 = bbase[0];
                uint32_t b1 = bbase[4];
                MMA_TF32(s[j][0], s[j][1], s[j][2], s[j][3], a0, a1, a2, a3, b0, b1);
            }
        }

        // ---- online softmax (rows gr and gr+8 of warp tile) ----
        float mx0 = -INFINITY, mx1 = -INFINITY;
        #pragma unroll
        for (int j = 0; j < 8; ++j) {
            s[j][0] *= scale; s[j][1] *= scale; s[j][2] *= scale; s[j][3] *= scale;
            mx0 = fmaxf(mx0, fmaxf(s[j][0], s[j][1]));
            mx1 = fmaxf(mx1, fmaxf(s[j][2], s[j][3]));
        }
        #pragma unroll
        for (int off = 1; off <= 2; off <<= 1) {
            mx0 = fmaxf(mx0, __shfl_xor_sync(0xffffffffu, mx0, off));
            mx1 = fmaxf(mx1, __shfl_xor_sync(0xffffffffu, mx1, off));
        }
        float m0n = fmaxf(m0, mx0);
        float m1n = fmaxf(m1, mx1);
        float al0 = __expf(m0 - m0n);
        float al1 = __expf(m1 - m1n);
        float rs0 = 0.f, rs1 = 0.f;
        uint32_t* prow0 = Ps + (wq + gr) * ALDP;
        uint32_t* prow1 = Ps + (wq + gr + 8) * ALDP;
        #pragma unroll
        for (int j = 0; j < 8; ++j) {
            float p0 = __expf(s[j][0] - m0n);
            float p1 = __expf(s[j][1] - m0n);
            float p2 = __expf(s[j][2] - m1n);
            float p3 = __expf(s[j][3] - m1n);
            rs0 += p0 + p1; rs1 += p2 + p3;
            int c = 8*j + 2*gc;
            prow0[c]     = f2tf32(p0);
            prow0[c + 1] = f2tf32(p1);
            prow1[c]     = f2tf32(p2);
            prow1[c + 1] = f2tf32(p3);
        }
        #pragma unroll
        for (int off = 1; off <= 2; off <<= 1) {
            rs0 += __shfl_xor_sync(0xffffffffu, rs0, off);
            rs1 += __shfl_xor_sync(0xffffffffu, rs1, off);
        }
        l0 = l0 * al0 + rs0;
        l1 = l1 * al1 + rs1;
        m0 = m0n; m1 = m1n;
        #pragma unroll
        for (int j = 0; j < 16; ++j) {
            o[j][0] *= al0; o[j][1] *= al0;
            o[j][2] *= al1; o[j][3] *= al1;
        }
        __syncwarp();

        // ---- O += P @ V : 8 ksteps x 16 n-atoms; V = Ks cols [0,128) ----
        #pragma unroll 2
        for (int ks = 0; ks < 8; ++ks) {
            const int k0 = ks * 8;
            const uint32_t* pbase = Ps + (wq + gr) * ALDP + k0 + gc;
            uint32_t a0 = pbase[0];
            uint32_t a2 = pbase[4];
            uint32_t a1 = pbase[8 * ALDP];
            uint32_t a3 = pbase[8 * ALDP + 4];
            #pragma unroll
            for (int j = 0; j < 16; ++j) {
                uint32_t b0 = Ks[(k0 + gc) * ALDQ + 8*j + gr];
                uint32_t b1 = Ks[(k0 + gc + 4) * ALDQ + 8*j + gr];
                MMA_TF32(o[j][0], o[j][1], o[j][2], o[j][3], a0, a1, a2, a3, b0, b1);
            }
        }
        __syncwarp();
    }

    // ---- epilogue ----
    float inv0 = 1.0f / l0;
    float inv1 = 1.0f / l1;
    size_t r0 = (tok0 + q0 + wq + gr) * DMODEL + h * DHD;
    size_t r1 = (tok0 + q0 + wq + gr + 8) * DMODEL + h * DHD;
    #pragma unroll
    for (int j = 0; j < 16; ++j) {
        int c = 8*j + 2*gc;
        *(float2*)(out + r0 + c) = make_float2(o[j][0] * inv0, o[j][1] * inv0);
        *(float2*)(out + r1 + c) = make_float2(o[j][2] * inv1, o[j][3] * inv1);
    }
}

// ================= host launch =================
static inline void launch_gemm_mma(const float* A, const float* Bt, const float* bias,
                                   float* C, int M, int N, int K)
{
    dim3 grid(N / BN, M / BM);
    gemm_mma<<<grid, 256>>>(A, Bt, bias, C, M, N, K);
}
static inline void launch_transpose(const float* in, float* out, int K, int N)
{
    transpose32<<<dim3(N / 32, K / 32), dim3(32, 8)>>>(in, out, K, N);
}

extern "C" void kernel_launch(void* const* d_in, const int* in_sizes, int n_in,
                              void* d_out, int out_size)
{
    (void)in_sizes; (void)n_in; (void)out_size;
    const float* x   = (const float*)d_in[0];
    const float* Wd  = (const float*)d_in[1];
    const float* bd  = (const float*)d_in[2];
    const float* Wu  = (const float*)d_in[3];
    const float* bu  = (const float*)d_in[4];
    const float* Wqd = (const float*)d_in[5];
    const float* bqd = (const float*)d_in[6];
    const float* Wqu = (const float*)d_in[7];
    const float* bqu = (const float*)d_in[8];
    const float* Wqr = (const float*)d_in[9];
    const float* bqr = (const float*)d_in[10];
    const float* Wkr = (const float*)d_in[11];
    const float* bkr = (const float*)d_in[12];
    const float* Wo  = (const float*)d_in[13];
    const float* bo  = (const float*)d_in[14];
    float* out = (float*)d_out;

    float *kvc, *kvup, *qcmp, *qcb, *qrb, *krb, *attn;
    float *wdT, *wuT, *wqdT, *wquT, *wqrT, *wkrT, *woT;
    cudaGetSymbolAddress((void**)&kvc,  g_kvc);
    cudaGetSymbolAddress((void**)&kvup, g_kvup);
    cudaGetSymbolAddress((void**)&qcmp, g_qcmp);
    cudaGetSymbolAddress((void**)&qcb,  g_qc);
    cudaGetSymbolAddress((void**)&qrb,  g_qr);
    cudaGetSymbolAddress((void**)&krb,  g_kr);
    cudaGetSymbolAddress((void**)&attn, g_attn);
    cudaGetSymbolAddress((void**)&wdT,  g_wdT);
    cudaGetSymbolAddress((void**)&wuT,  g_wuT);
    cudaGetSymbolAddress((void**)&wqdT, g_wqdT);
    cudaGetSymbolAddress((void**)&wquT, g_wquT);
    cudaGetSymbolAddress((void**)&wqrT, g_wqrT);
    cudaGetSymbolAddress((void**)&wkrT, g_wkrT);
    cudaGetSymbolAddress((void**)&woT,  g_woT);

    cudaFuncSetAttribute(flash_mma, cudaFuncAttributeMaxDynamicSharedMemorySize,
                         FL_SMEM);

    // weight transposes (K-major B for mma row.col)
    launch_transpose(Wd,  wdT,  DMODEL, DC);
    launch_transpose(Wu,  wuT,  DC,     DMODEL);
    launch_transpose(Wqd, wqdT, DMODEL, DCOMP);
    launch_transpose(Wqu, wquT, DCOMP,  DMODEL);
    launch_transpose(Wqr, wqrT, DCOMP,  NH*DRP);
    launch_transpose(Wkr, wkrT, DMODEL, NH*DRP);
    launch_transpose(Wo,  woT,  DMODEL, DMODEL);

    // projections (tf32 mma.sync)
    launch_gemm_mma(x,    wdT,  bd,  kvc,  NTOK, DC,     DMODEL);
    launch_gemm_mma(kvc,  wuT,  bu,  kvup, NTOK, DMODEL, DC);
    launch_gemm_mma(x,    wqdT, bqd, qcmp, NTOK, DCOMP,  DMODEL);
    launch_gemm_mma(qcmp, wquT, bqu, qcb,  NTOK, DMODEL, DCOMP);
    launch_gemm_mma(qcmp, wqrT, bqr, qrb,  NTOK, NH*DRP, DCOMP);
    launch_gemm_mma(x,    wkrT, bkr, krb,  NTOK, NH*DRP, DMODEL);

    // rope
    {
        int n = NTOK * NH * 32;
        int blocks = (n + 255) / 256;
        rope_kernel<<<blocks, 256>>>(qrb, n);
        rope_kernel<<<blocks, 256>>>(krb, n);
    }

    // attention (tf32 mma flash)
    {
        dim3 grid(SS / 128, NH, BB);
        flash_mma<<<grid, 256, FL_SMEM>>>(qcb, qrb, kvup, krb, attn);
    }

    // output projection
    launch_gemm_mma(attn, woT, bo, out, NTOK, DMODEL, DMODEL);
}

// round 5
// speedup vs baseline: 2.8314x; 1.0266x over previous
#include <cuda_runtime.h>
#include <math.h>
#include <stdint.h>

#define BB 2
#define SS 2048
#define NH 16
#define DHD 128
#define DRP 64
#define DQK 192
#define DMODEL 2048
#define DC 512
#define DCOMP 768
#define NTOK (BB*SS)

// ---------------- scratch (static device globals; no allocation) ----------------
__device__ float g_xt  [NTOK*DMODEL];    // tf32-rounded x
__device__ float g_kvc [NTOK*DC];
__device__ float g_kvup[NTOK*DMODEL];
__device__ float g_qcmp[NTOK*DCOMP];
__device__ float g_qc  [NTOK*DMODEL];
__device__ float g_qr  [NTOK*NH*DRP];
__device__ float g_kr  [NTOK*NH*DRP];
__device__ float g_attn[NTOK*DMODEL];
// transposed (and tf32-rounded) weights
__device__ float g_wdT [DC*DMODEL];
__device__ float g_wuT [DMODEL*DC];
__device__ float g_wqdT[DCOMP*DMODEL];
__device__ float g_wquT[DMODEL*DCOMP];
__device__ float g_wqrT[(NH*DRP)*DCOMP];
__device__ float g_wkrT[(NH*DRP)*DMODEL];
__device__ float g_woT [DMODEL*DMODEL];

__device__ __forceinline__ uint32_t f2tf32(float x) {
    uint32_t r;
    asm("cvt.rna.tf32.f32 %0, %1;" : "=r"(r) : "f"(x));
    return r;
}
__device__ __forceinline__ float roundtf(float x) {
    return __uint_as_float(f2tf32(x));
}
__device__ __forceinline__ uint32_t smem_u32(const void* p) {
    uint32_t a;
    asm("{ .reg .u64 t; cvta.to.shared.u64 t, %1; cvt.u32.u64 %0, t; }"
        : "=r"(a) : "l"(p));
    return a;
}

#define MMA_TF32(d0,d1,d2,d3, a0,a1,a2,a3, b0,b1) \
    asm volatile( \
        "mma.sync.aligned.m16n8k8.row.col.f32.tf32.tf32.f32 " \
        "{%0,%1,%2,%3}, {%4,%5,%6,%7}, {%8,%9}, {%0,%1,%2,%3};" \
        : "+f"(d0), "+f"(d1), "+f"(d2), "+f"(d3) \
        : "r"(a0), "r"(a1), "r"(a2), "r"(a3), "r"(b0), "r"(b1))

#define CP_ASYNC16(dst, src) \
    asm volatile("cp.async.cg.shared.global [%0], [%1], 16;" \
                 :: "r"(dst), "l"(src))
#define CP_COMMIT() asm volatile("cp.async.commit_group;" ::: "memory")
#define CP_WAIT2()  asm volatile("cp.async.wait_group 2;" ::: "memory")

// ================= rounding pass for x =================
__global__ void round_tf32_kernel(const float* __restrict__ in,
                                  float* __restrict__ out, int n4)
{
    int i = blockIdx.x * blockDim.x + threadIdx.x;
    if (i >= n4) return;
    float4 v = ((const float4*)in)[i];
    v.x = roundtf(v.x); v.y = roundtf(v.y);
    v.z = roundtf(v.z); v.w = roundtf(v.w);
    ((float4*)out)[i] = v;
}

// ================= weight transpose + tf32 round: out[n][k] = rnd(in[k][n]) ====
__global__ void transpose32(const float* __restrict__ in, float* __restrict__ out,
                            int K, int N)
{
    __shared__ float t[32][33];
    int n0 = blockIdx.x * 32, k0 = blockIdx.y * 32;
    int tx = threadIdx.x, ty = threadIdx.y;  // (32, 8)
    #pragma unroll
    for (int i = 0; i < 4; ++i)
        t[ty + 8*i][tx] = in[(size_t)(k0 + ty + 8*i) * N + n0 + tx];
    __syncthreads();
    #pragma unroll
    for (int i = 0; i < 4; ++i)
        out[(size_t)(n0 + ty + 8*i) * K + k0 + tx] = roundtf(t[tx][ty + 8*i]);
}

// ================= cp.async pipelined tf32 GEMM ==========================
// C[M,N] = A[M,K] @ Bt[N,K]^T + bias. Inputs pre-rounded to tf32.
// CTA 128x128, BK=16, 4 stages, 128 threads = 4 warps (2x2), warp tile 64x64.
#define GBM 128
#define GBN 128
#define GBK 16
#define GSTG 4
#define GLDW 20                       // words per smem row (16 data + 4 pad)
#define GSTG_WORDS ((GBM + GBN) * GLDW)
#define GEMM_SMEM (GSTG * GSTG_WORDS * 4)   // 81920 B

__global__ __launch_bounds__(128, 2) void gemm_cp(
    const float* __restrict__ A, const float* __restrict__ Bt,
    const float* __restrict__ bias, float* __restrict__ C,
    int M, int N, int K, int round_out)
{
    extern __shared__ uint32_t gsm[];
    const int tid  = threadIdx.x;
    const int wid  = tid >> 5;
    const int lane = tid & 31;
    const int wm = wid >> 1, wn = wid & 1;
    const int gr = lane >> 2, gc = lane & 3;
    const int wr = wm * 64,  wc = wn * 64;

    const int row0 = blockIdx.y * GBM;
    const int col0 = blockIdx.x * GBN;
    const float* Ag = A  + (size_t)row0 * K;
    const float* Bg = Bt + (size_t)col0 * K;

    // cp.async mapping: chunk c -> row (tid>>2)+32c, col (tid&3)*4 (coalesced 64B)
    const int crow = tid >> 2;
    const int ccol = (tid & 3) * 4;
    const uint32_t smbase = smem_u32(gsm);

    const int niter = K / GBK;

    // ---- stage issue helper (manually inlined via macro-ish lambda) ----
    auto issue_stage = [&](int s, int it) {
        const int ko = it * GBK;
        uint32_t as = smbase + (uint32_t)(s * GSTG_WORDS) * 4u;
        uint32_t bs = as + (uint32_t)(GBM * GLDW) * 4u;
        #pragma unroll
        for (int c = 0; c < 4; ++c) {
            int r = crow + 32 * c;
            CP_ASYNC16(as + (uint32_t)(r * GLDW + ccol) * 4u,
                       Ag + (size_t)r * K + ko + ccol);
            CP_ASYNC16(bs + (uint32_t)(r * GLDW + ccol) * 4u,
                       Bg + (size_t)r * K + ko + ccol);
        }
    };

    float acc[4][8][4];
    #pragma unroll
    for (int i = 0; i < 4; ++i)
        #pragma unroll
        for (int j = 0; j < 8; ++j)
            #pragma unroll
            for (int c = 0; c < 4; ++c) acc[i][j][c] = 0.f;

    // prologue: fill 3 stages
    #pragma unroll
    for (int s = 0; s < GSTG - 1; ++s) { issue_stage(s, s); CP_COMMIT(); }

    for (int it = 0; it < niter; ++it) {
        CP_WAIT2();
        __syncthreads();

        // issue next stage (buffer consumed at it-1; protected by the sync)
        if (it + GSTG - 1 < niter) issue_stage((it + GSTG - 1) % GSTG, it + GSTG - 1);
        CP_COMMIT();   // commit every iter (possibly empty) to keep counts sound

        const uint32_t* As = gsm + (it % GSTG) * GSTG_WORDS;
        const uint32_t* Bs = As + GBM * GLDW;

        #pragma unroll
        for (int ks = 0; ks < 2; ++ks) {
            const int k0 = ks * 8;
            uint32_t a[4][4], b[8][2];
            #pragma unroll
            for (int i = 0; i < 4; ++i) {
                const uint32_t* base = As + (wr + 16*i + gr) * GLDW + k0 + gc;
                a[i][0] = base[0];
                a[i][2] = base[4];
                a[i][1] = base[8 * GLDW];
                a[i][3] = base[8 * GLDW + 4];
            }
            #pragma unroll
            for (int j = 0; j < 8; ++j) {
                const uint32_t* base = Bs + (wc + 8*j + gr) * GLDW + k0 + gc;
                b[j][0] = base[0];
                b[j][1] = base[4];
            }
            #pragma unroll
            for (int i = 0; i < 4; ++i)
                #pragma unroll
                for (int j = 0; j < 8; ++j)
                    MMA_TF32(acc[i][j][0], acc[i][j][1], acc[i][j][2], acc[i][j][3],
                             a[i][0], a[i][1], a[i][2], a[i][3], b[j][0], b[j][1]);
        }
        __syncthreads();
    }

    // ---- epilogue ----
    #pragma unroll
    for (int j = 0; j < 8; ++j) {
        int c = col0 + wc + 8*j + 2*gc;
        float bv0 = bias[c], bv1 = bias[c + 1];
        #pragma unroll
        for (int i = 0; i < 4; ++i) {
            int r = row0 + wr + 16*i + gr;
            float f0 = acc[i][j][0] + bv0, f1 = acc[i][j][1] + bv1;
            float f2 = acc[i][j][2] + bv0, f3 = acc[i][j][3] + bv1;
            if (round_out) {
                f0 = roundtf(f0); f1 = roundtf(f1);
                f2 = roundtf(f2); f3 = roundtf(f3);
            }
            *(float2*)(C + (size_t)r * N + c)       = make_float2(f0, f1);
            *(float2*)(C + (size_t)(r + 8) * N + c) = make_float2(f2, f3);
        }
    }
}

// ================= RoPE (in place), rounds output to tf32 =================
__global__ void rope_kernel(float* __restrict__ buf, int n)
{
    int idx = blockIdx.x * blockDim.x + threadIdx.x;
    if (idx >= n) return;
    int i = idx & 31;
    int h = (idx >> 5) & (NH - 1);
    int t = idx >> 9;
    int pos = t & (SS - 1);

    float freq = exp2f(-13.287712379549449f * (float)i / 32.0f);
    float ang = (float)pos * freq;
    float sn, cs;
    sincosf(ang, &sn, &cs);

    float* p = buf + (size_t)t * (NH * DRP) + h * DRP + 2 * i;
    float x1 = p[0], x2 = p[1];
    p[0] = roundtf(x1 * cs - x2 * sn);
    p[1] = roundtf(x1 * sn + x2 * cs);
}

// ================= flash attention with tf32 mma.sync =================
// Inputs pre-rounded to tf32 -> pure bit copies into smem.
#define ALDQ 196
#define ALDP 68
#define FL_SMEM ((128*ALDQ + 64*ALDQ + 128*ALDP) * 4)   // 185,344 B

__global__ __launch_bounds__(256, 1) void flash_mma(
    const float* __restrict__ qc, const float* __restrict__ qr,
    const float* __restrict__ kvup, const float* __restrict__ kr,
    float* __restrict__ out)
{
    extern __shared__ uint32_t sm[];
    uint32_t* Qs = sm;                       // [128][196]
    uint32_t* Ks = sm + 128 * ALDQ;          // [64][196]
    uint32_t* Ps = Ks + 64 * ALDQ;           // [128][68]

    const int tid  = threadIdx.x;
    const int wid  = tid >> 5;
    const int lane = tid & 31;
    const int gr = lane >> 2;
    const int gc = lane & 3;
    const int wq = wid * 16;

    const int q0 = blockIdx.x * 128;
    const int h  = blockIdx.y;
    const int b  = blockIdx.z;
    const size_t tok0 = (size_t)b * SS;

    // ---- load Q tile (already tf32): q_c cols [0,128), q_r cols [128,192) ----
    for (int idx = tid; idx < 128 * 32; idx += 256) {
        int r = idx >> 5, c4 = (idx & 31) * 4;
        *(uint4*)(Qs + r * ALDQ + c4) =
            *(const uint4*)(qc + (tok0 + q0 + r) * DMODEL + h * DHD + c4);
    }
    for (int idx = tid; idx < 128 * 16; idx += 256) {
        int r = idx >> 4, c4 = (idx & 15) * 4;
        *(uint4*)(Qs + r * ALDQ + 128 + c4) =
            *(const uint4*)(qr + (tok0 + q0 + r) * (NH * DRP) + h * DRP + c4);
    }

    float m0 = -INFINITY, m1 = -INFINITY, l0 = 0.f, l1 = 0.f;
    float o[16][4];
    #pragma unroll
    for (int j = 0; j < 16; ++j)
        #pragma unroll
        for (int c = 0; c < 4; ++c) o[j][c] = 0.f;

    const float scale = 0.08838834764831845f;  // 1/sqrt(128)

    for (int kt = 0; kt < SS / 64; ++kt) {
        const int k0tok = kt * 64;
        __syncthreads();
        for (int idx = tid; idx < 64 * 32; idx += 256) {
            int r = idx >> 5, c4 = (idx & 31) * 4;
            *(uint4*)(Ks + r * ALDQ + c4) =
                *(const uint4*)(kvup + (tok0 + k0tok + r) * DMODEL + h * DHD + c4);
        }
        for (int idx = tid; idx < 64 * 16; idx += 256) {
            int r = idx >> 4, c4 = (idx & 15) * 4;
            *(uint4*)(Ks + r * ALDQ + 128 + c4) =
                *(const uint4*)(kr + (tok0 + k0tok + r) * (NH * DRP) + h * DRP + c4);
        }
        __syncthreads();

        float s[8][4];
        #pragma unroll
        for (int j = 0; j < 8; ++j)
            #pragma unroll
            for (int c = 0; c < 4; ++c) s[j][c] = 0.f;

        #pragma unroll 4
        for (int ks = 0; ks < 24; ++ks) {
            const int k0 = ks * 8;
            const uint32_t* abase = Qs + (wq + gr) * ALDQ + k0 + gc;
            uint32_t a0 = abase[0];
            uint32_t a2 = abase[4];
            uint32_t a1 = abase[8 * ALDQ];
            uint32_t a3 = abase[8 * ALDQ + 4];
            #pragma unroll
            for (int j = 0; j < 8; ++j) {
                const uint32_t* bbase = Ks + (8*j + gr) * ALDQ + k0 + gc;
                uint32_t b0 = bbase[0];
                uint32_t b1 = bbase[4];
                MMA_TF32(s[j][0], s[j][1], s[j][2], s[j][3], a0, a1, a2, a3, b0, b1);
            }
        }

        float mx0 = -INFINITY, mx1 = -INFINITY;
        #pragma unroll
        for (int j = 0; j < 8; ++j) {
            s[j][0] *= scale; s[j][1] *= scale; s[j][2] *= scale; s[j][3] *= scale;
            mx0 = fmaxf(mx0, fmaxf(s[j][0], s[j][1]));
            mx1 = fmaxf(mx1, fmaxf(s[j][2], s[j][3]));
        }
        #pragma unroll
        for (int off = 1; off <= 2; off <<= 1) {
            mx0 = fmaxf(mx0, __shfl_xor_sync(0xffffffffu, mx0, off));
            mx1 = fmaxf(mx1, __shfl_xor_sync(0xffffffffu, mx1, off));
        }
        float m0n = fmaxf(m0, mx0);
        float m1n = fmaxf(m1, mx1);
        float al0 = __expf(m0 - m0n);
        float al1 = __expf(m1 - m1n);
        float rs0 = 0.f, rs1 = 0.f;
        uint32_t* prow0 = Ps + (wq + gr) * ALDP;
        uint32_t* prow1 = Ps + (wq + gr + 8) * ALDP;
        #pragma unroll
        for (int j = 0; j < 8; ++j) {
            float p0 = __expf(s[j][0] - m0n);
            float p1 = __expf(s[j][1] - m0n);
            float p2 = __expf(s[j][2] - m1n);
            float p3 = __expf(s[j][3] - m1n);
            rs0 += p0 + p1; rs1 += p2 + p3;
            int c = 8*j + 2*gc;
            prow0[c]     = f2tf32(p0);
            prow0[c + 1] = f2tf32(p1);
            prow1[c]     = f2tf32(p2);
            prow1[c + 1] = f2tf32(p3);
        }
        #pragma unroll
        for (int off = 1; off <= 2; off <<= 1) {
            rs0 += __shfl_xor_sync(0xffffffffu, rs0, off);
            rs1 += __shfl_xor_sync(0xffffffffu, rs1, off);
        }
        l0 = l0 * al0 + rs0;
        l1 = l1 * al1 + rs1;
        m0 = m0n; m1 = m1n;
        #pragma unroll
        for (int j = 0; j < 16; ++j) {
            o[j][0] *= al0; o[j][1] *= al0;
            o[j][2] *= al1; o[j][3] *= al1;
        }
        __syncwarp();

        #pragma unroll 2
        for (int ks = 0; ks < 8; ++ks) {
            const int k0 = ks * 8;
            const uint32_t* pbase = Ps + (wq + gr) * ALDP + k0 + gc;
            uint32_t a0 = pbase[0];
            uint32_t a2 = pbase[4];
            uint32_t a1 = pbase[8 * ALDP];
            uint32_t a3 = pbase[8 * ALDP + 4];
            #pragma unroll
            for (int j = 0; j < 16; ++j) {
                uint32_t b0 = Ks[(k0 + gc) * ALDQ + 8*j + gr];
                uint32_t b1 = Ks[(k0 + gc + 4) * ALDQ + 8*j + gr];
                MMA_TF32(o[j][0], o[j][1], o[j][2], o[j][3], a0, a1, a2, a3, b0, b1);
            }
        }
        __syncwarp();
    }

    // ---- epilogue (write tf32-rounded attn for the Wo GEMM) ----
    float inv0 = 1.0f / l0;
    float inv1 = 1.0f / l1;
    size_t r0 = (tok0 + q0 + wq + gr) * DMODEL + h * DHD;
    size_t r1 = (tok0 + q0 + wq + gr + 8) * DMODEL + h * DHD;
    #pragma unroll
    for (int j = 0; j < 16; ++j) {
        int c = 8*j + 2*gc;
        *(float2*)(out + r0 + c) =
            make_float2(roundtf(o[j][0] * inv0), roundtf(o[j][1] * inv0));
        *(float2*)(out + r1 + c) =
            make_float2(roundtf(o[j][2] * inv1), roundtf(o[j][3] * inv1));
    }
}

// ================= host launch =================
static inline void launch_gemm(const float* A, const float* Bt, const float* bias,
                               float* C, int M, int N, int K, int round_out)
{
    dim3 grid(N / GBN, M / GBM);
    gemm_cp<<<grid, 128, GEMM_SMEM>>>(A, Bt, bias, C, M, N, K, round_out);
}
static inline void launch_transpose(const float* in, float* out, int K, int N)
{
    transpose32<<<dim3(N / 32, K / 32), dim3(32, 8)>>>(in, out, K, N);
}

extern "C" void kernel_launch(void* const* d_in, const int* in_sizes, int n_in,
                              void* d_out, int out_size)
{
    (void)in_sizes; (void)n_in; (void)out_size;
    const float* x   = (const float*)d_in[0];
    const float* Wd  = (const float*)d_in[1];
    const float* bd  = (const float*)d_in[2];
    const float* Wu  = (const float*)d_in[3];
    const float* bu  = (const float*)d_in[4];
    const float* Wqd = (const float*)d_in[5];
    const float* bqd = (const float*)d_in[6];
    const float* Wqu = (const float*)d_in[7];
    const float* bqu = (const float*)d_in[8];
    const float* Wqr = (const float*)d_in[9];
    const float* bqr = (const float*)d_in[10];
    const float* Wkr = (const float*)d_in[11];
    const float* bkr = (const float*)d_in[12];
    const float* Wo  = (const float*)d_in[13];
    const float* bo  = (const float*)d_in[14];
    float* out = (float*)d_out;

    float *xt, *kvc, *kvup, *qcmp, *qcb, *qrb, *krb, *attn;
    float *wdT, *wuT, *wqdT, *wquT, *wqrT, *wkrT, *woT;
    cudaGetSymbolAddress((void**)&xt,   g_xt);
    cudaGetSymbolAddress((void**)&kvc,  g_kvc);
    cudaGetSymbolAddress((void**)&kvup, g_kvup);
    cudaGetSymbolAddress((void**)&qcmp, g_qcmp);
    cudaGetSymbolAddress((void**)&qcb,  g_qc);
    cudaGetSymbolAddress((void**)&qrb,  g_qr);
    cudaGetSymbolAddress((void**)&krb,  g_kr);
    cudaGetSymbolAddress((void**)&attn, g_attn);
    cudaGetSymbolAddress((void**)&wdT,  g_wdT);
    cudaGetSymbolAddress((void**)&wuT,  g_wuT);
    cudaGetSymbolAddress((void**)&wqdT, g_wqdT);
    cudaGetSymbolAddress((void**)&wquT, g_wquT);
    cudaGetSymbolAddress((void**)&wqrT, g_wqrT);
    cudaGetSymbolAddress((void**)&wkrT, g_wkrT);
    cudaGetSymbolAddress((void**)&woT,  g_woT);

    cudaFuncSetAttribute(gemm_cp, cudaFuncAttributeMaxDynamicSharedMemorySize,
                         GEMM_SMEM);
    cudaFuncSetAttribute(flash_mma, cudaFuncAttributeMaxDynamicSharedMemorySize,
                         FL_SMEM);

    // pre-round x; transpose+round weights
    round_tf32_kernel<<<(NTOK*DMODEL/4 + 255)/256, 256>>>(x, xt, NTOK*DMODEL/4);
    launch_transpose(Wd,  wdT,  DMODEL, DC);
    launch_transpose(Wu,  wuT,  DC,     DMODEL);
    launch_transpose(Wqd, wqdT, DMODEL, DCOMP);
    launch_transpose(Wqu, wquT, DCOMP,  DMODEL);
    launch_transpose(Wqr, wqrT, DCOMP,  NH*DRP);
    launch_transpose(Wkr, wkrT, DMODEL, NH*DRP);
    launch_transpose(Wo,  woT,  DMODEL, DMODEL);

    // projections (cp.async tf32 mma pipeline); round_out=1 where the consumer
    // is another tf32 GEMM / flash; 0 where rope re-rounds or it's the output.
    launch_gemm(xt,   wdT,  bd,  kvc,  NTOK, DC,     DMODEL, 1);
    launch_gemm(kvc,  wuT,  bu,  kvup, NTOK, DMODEL, DC,     1);
    launch_gemm(xt,   wqdT, bqd, qcmp, NTOK, DCOMP,  DMODEL, 1);
    launch_gemm(qcmp, wquT, bqu, qcb,  NTOK, DMODEL, DCOMP,  1);
    launch_gemm(qcmp, wqrT, bqr, qrb,  NTOK, NH*DRP, DCOMP,  0);
    launch_gemm(xt,   wkrT, bkr, krb,  NTOK, NH*DRP, DMODEL, 0);

    // rope (rounds its outputs to tf32)
    {
        int n = NTOK * NH * 32;
        int blocks = (n + 255) / 256;
        rope_kernel<<<blocks, 256>>>(qrb, n);
        rope_kernel<<<blocks, 256>>>(krb, n);
    }

    // attention (tf32 mma flash; writes rounded attn)
    {
        dim3 grid(SS / 128, NH, BB);
        flash_mma<<<grid, 256, FL_SMEM>>>(qcb, qrb, kvup, krb, attn);
    }

    // output projection (full fp32 output)
    launch_gemm(attn, woT, bo, out, NTOK, DMODEL, DMODEL, 0);
}

// round 6
// speedup vs baseline: 2.8480x; 1.0058x over previous
#include <cuda_runtime.h>
#include <math.h>
#include <stdint.h>

#define BB 2
#define SS 2048
#define NH 16
#define DHD 128
#define DRP 64
#define DQK 192
#define DMODEL 2048
#define DC 512
#define DCOMP 768
#define NTOK (BB*SS)

// ---------------- scratch (static device globals; no allocation) ----------------
__device__ float g_xt  [NTOK*DMODEL];    // tf32-rounded x
__device__ float g_kvc [NTOK*DC];
__device__ float g_kvup[NTOK*DMODEL];
__device__ float g_qcmp[NTOK*DCOMP];
__device__ float g_qc  [NTOK*DMODEL];
__device__ float g_qr  [NTOK*NH*DRP];
__device__ float g_kr  [NTOK*NH*DRP];
__device__ float g_attn[NTOK*DMODEL];
// transposed (and tf32-rounded) weights
__device__ float g_wdT [DC*DMODEL];
__device__ float g_wuT [DMODEL*DC];
__device__ float g_wqdT[DCOMP*DMODEL];
__device__ float g_wquT[DMODEL*DCOMP];
__device__ float g_wqrT[(NH*DRP)*DCOMP];
__device__ float g_wkrT[(NH*DRP)*DMODEL];
__device__ float g_woT [DMODEL*DMODEL];

__device__ __forceinline__ uint32_t f2tf32(float x) {
    uint32_t r;
    asm("cvt.rna.tf32.f32 %0, %1;" : "=r"(r) : "f"(x));
    return r;
}
__device__ __forceinline__ float roundtf(float x) {
    return __uint_as_float(f2tf32(x));
}
__device__ __forceinline__ uint32_t smem_u32(const void* p) {
    uint32_t a;
    asm("{ .reg .u64 t; cvta.to.shared.u64 t, %1; cvt.u32.u64 %0, t; }"
        : "=r"(a) : "l"(p));
    return a;
}

#define MMA_TF32(d0,d1,d2,d3, a0,a1,a2,a3, b0,b1) \
    asm volatile( \
        "mma.sync.aligned.m16n8k8.row.col.f32.tf32.tf32.f32 " \
        "{%0,%1,%2,%3}, {%4,%5,%6,%7}, {%8,%9}, {%0,%1,%2,%3};" \
        : "+f"(d0), "+f"(d1), "+f"(d2), "+f"(d3) \
        : "r"(a0), "r"(a1), "r"(a2), "r"(a3), "r"(b0), "r"(b1))

#define CP_ASYNC16(dst, src) \
    asm volatile("cp.async.cg.shared.global [%0], [%1], 16;" \
                 :: "r"(dst), "l"(src))
#define CP_COMMIT() asm volatile("cp.async.commit_group;" ::: "memory")
#define CP_WAIT1()  asm volatile("cp.async.wait_group 1;" ::: "memory")

// ================= rounding pass for x =================
__global__ void round_tf32_kernel(const float* __restrict__ in,
                                  float* __restrict__ out, int n4)
{
    int i = blockIdx.x * blockDim.x + threadIdx.x;
    if (i >= n4) return;
    float4 v = ((const float4*)in)[i];
    v.x = roundtf(v.x); v.y = roundtf(v.y);
    v.z = roundtf(v.z); v.w = roundtf(v.w);
    ((float4*)out)[i] = v;
}

// ================= weight transpose + tf32 round: out[n][k] = rnd(in[k][n]) ====
__global__ void transpose32(const float* __restrict__ in, float* __restrict__ out,
                            int K, int N)
{
    __shared__ float t[32][33];
    int n0 = blockIdx.x * 32, k0 = blockIdx.y * 32;
    int tx = threadIdx.x, ty = threadIdx.y;  // (32, 8)
    #pragma unroll
    for (int i = 0; i < 4; ++i)
        t[ty + 8*i][tx] = in[(size_t)(k0 + ty + 8*i) * N + n0 + tx];
    __syncthreads();
    #pragma unroll
    for (int i = 0; i < 4; ++i)
        out[(size_t)(n0 + ty + 8*i) * K + k0 + tx] = roundtf(t[tx][ty + 8*i]);
}

// ================= cp.async 3-stage tf32 GEMM ==========================
// C[M,N] = A[M,K] @ Bt[N,K]^T + bias. Inputs pre-rounded to tf32.
// CTA 128x128, BK=32, 3 stages, 256 threads = 8 warps (2x4), warp tile 64x32.
// One __syncthreads per K-iteration; 64 MMAs per warp between barriers.
#define GBM 128
#define GBN 128
#define GBK 32
#define GSTG 3
#define GLDW 36                          // words per smem row (32 data + 4 pad)
#define GSTG_WORDS ((GBM + GBN) * GLDW)  // 9216 words
#define GEMM_SMEM (GSTG * GSTG_WORDS * 4)   // 110,592 B

__global__ __launch_bounds__(256, 1) void gemm_cp(
    const float* __restrict__ A, const float* __restrict__ Bt,
    const float* __restrict__ bias, float* __restrict__ C,
    int M, int N, int K, int round_out)
{
    extern __shared__ uint32_t gsm[];
    const int tid  = threadIdx.x;
    const int wid  = tid >> 5;
    const int lane = tid & 31;
    const int wm = wid >> 2, wn = wid & 3;   // 2x4 warp grid
    const int gr = lane >> 2, gc = lane & 3;
    const int wr = wm * 64,  wc = wn * 32;

    const int row0 = blockIdx.y * GBM;
    const int col0 = blockIdx.x * GBN;
    const float* Ag = A  + (size_t)row0 * K;
    const float* Bg = Bt + (size_t)col0 * K;

    // cp.async mapping: 128 rows x 8 float4 per matrix; 256 threads -> 4 each
    const int crow = tid >> 3;          // 0..31
    const int ccol = (tid & 7) * 4;     // 0,4,...,28
    const uint32_t smbase = smem_u32(gsm);

    const int niter = K / GBK;

    auto issue_stage = [&](int it) {
        const int s = it % GSTG;
        const int ko = it * GBK;
        uint32_t as = smbase + (uint32_t)(s * GSTG_WORDS) * 4u;
        uint32_t bs = as + (uint32_t)(GBM * GLDW) * 4u;
        #pragma unroll
        for (int c = 0; c < 4; ++c) {
            int r = crow + 32 * c;
            CP_ASYNC16(as + (uint32_t)(r * GLDW + ccol) * 4u,
                       Ag + (size_t)r * K + ko + ccol);
            CP_ASYNC16(bs + (uint32_t)(r * GLDW + ccol) * 4u,
                       Bg + (size_t)r * K + ko + ccol);
        }
    };

    float acc[4][4][4];
    #pragma unroll
    for (int i = 0; i < 4; ++i)
        #pragma unroll
        for (int j = 0; j < 4; ++j)
            #pragma unroll
            for (int c = 0; c < 4; ++c) acc[i][j][c] = 0.f;

    // prologue: stages 0 and 1
    issue_stage(0); CP_COMMIT();
    issue_stage(1); CP_COMMIT();

    for (int it = 0; it < niter; ++it) {
        CP_WAIT1();          // stage `it` data arrived (<=1 pending group)
        __syncthreads();     // all warps done with the buffer we're about to refill

        if (it + 2 < niter) issue_stage(it + 2);
        CP_COMMIT();         // commit every iter (possibly empty): counts stay sound

        const uint32_t* As = gsm + (it % GSTG) * GSTG_WORDS;
        const uint32_t* Bs = As + GBM * GLDW;

        #pragma unroll
        for (int ks = 0; ks < 4; ++ks) {
            const int k0 = ks * 8;
            uint32_t a[4][4], b[4][2];
            #pragma unroll
            for (int i = 0; i < 4; ++i) {
                const uint32_t* base = As + (wr + 16*i + gr) * GLDW + k0 + gc;
                a[i][0] = base[0];
                a[i][2] = base[4];
                a[i][1] = base[8 * GLDW];
                a[i][3] = base[8 * GLDW + 4];
            }
            #pragma unroll
            for (int j = 0; j < 4; ++j) {
                const uint32_t* base = Bs + (wc + 8*j + gr) * GLDW + k0 + gc;
                b[j][0] = base[0];
                b[j][1] = base[4];
            }
            #pragma unroll
            for (int i = 0; i < 4; ++i)
                #pragma unroll
                for (int j = 0; j < 4; ++j)
                    MMA_TF32(acc[i][j][0], acc[i][j][1], acc[i][j][2], acc[i][j][3],
                             a[i][0], a[i][1], a[i][2], a[i][3], b[j][0], b[j][1]);
        }
    }

    // ---- epilogue ----
    #pragma unroll
    for (int j = 0; j < 4; ++j) {
        int c = col0 + wc + 8*j + 2*gc;
        float bv0 = bias[c], bv1 = bias[c + 1];
        #pragma unroll
        for (int i = 0; i < 4; ++i) {
            int r = row0 + wr + 16*i + gr;
            float f0 = acc[i][j][0] + bv0, f1 = acc[i][j][1] + bv1;
            float f2 = acc[i][j][2] + bv0, f3 = acc[i][j][3] + bv1;
            if (round_out) {
                f0 = roundtf(f0); f1 = roundtf(f1);
                f2 = roundtf(f2); f3 = roundtf(f3);
            }
            *(float2*)(C + (size_t)r * N + c)       = make_float2(f0, f1);
            *(float2*)(C + (size_t)(r + 8) * N + c) = make_float2(f2, f3);
        }
    }
}

// ================= RoPE (in place), rounds output to tf32 =================
__global__ void rope_kernel(float* __restrict__ buf, int n)
{
    int idx = blockIdx.x * blockDim.x + threadIdx.x;
    if (idx >= n) return;
    int i = idx & 31;
    int h = (idx >> 5) & (NH - 1);
    int t = idx >> 9;
    int pos = t & (SS - 1);

    float freq = exp2f(-13.287712379549449f * (float)i / 32.0f);
    float ang = (float)pos * freq;
    float sn, cs;
    sincosf(ang, &sn, &cs);

    float* p = buf + (size_t)t * (NH * DRP) + h * DRP + 2 * i;
    float x1 = p[0], x2 = p[1];
    p[0] = roundtf(x1 * cs - x2 * sn);
    p[1] = roundtf(x1 * sn + x2 * cs);
}

// ================= flash attention with tf32 mma.sync =================
// Inputs pre-rounded to tf32 -> pure bit copies into smem.
#define ALDQ 196
#define ALDP 68
#define FL_SMEM ((128*ALDQ + 64*ALDQ + 128*ALDP) * 4)   // 185,344 B

__global__ __launch_bounds__(256, 1) void flash_mma(
    const float* __restrict__ qc, const float* __restrict__ qr,
    const float* __restrict__ kvup, const float* __restrict__ kr,
    float* __restrict__ out)
{
    extern __shared__ uint32_t sm[];
    uint32_t* Qs = sm;                       // [128][196]
    uint32_t* Ks = sm + 128 * ALDQ;          // [64][196]
    uint32_t* Ps = Ks + 64 * ALDQ;           // [128][68]

    const int tid  = threadIdx.x;
    const int wid  = tid >> 5;
    const int lane = tid & 31;
    const int gr = lane >> 2;
    const int gc = lane & 3;
    const int wq = wid * 16;

    const int q0 = blockIdx.x * 128;
    const int h  = blockIdx.y;
    const int b  = blockIdx.z;
    const size_t tok0 = (size_t)b * SS;

    for (int idx = tid; idx < 128 * 32; idx += 256) {
        int r = idx >> 5, c4 = (idx & 31) * 4;
        *(uint4*)(Qs + r * ALDQ + c4) =
            *(const uint4*)(qc + (tok0 + q0 + r) * DMODEL + h * DHD + c4);
    }
    for (int idx = tid; idx < 128 * 16; idx += 256) {
        int r = idx >> 4, c4 = (idx & 15) * 4;
        *(uint4*)(Qs + r * ALDQ + 128 + c4) =
            *(const uint4*)(qr + (tok0 + q0 + r) * (NH * DRP) + h * DRP + c4);
    }

    float m0 = -INFINITY, m1 = -INFINITY, l0 = 0.f, l1 = 0.f;
    float o[16][4];
    #pragma unroll
    for (int j = 0; j < 16; ++j)
        #pragma unroll
        for (int c = 0; c < 4; ++c) o[j][c] = 0.f;

    const float scale = 0.08838834764831845f;  // 1/sqrt(128)

    for (int kt = 0; kt < SS / 64; ++kt) {
        const int k0tok = kt * 64;
        __syncthreads();
        for (int idx = tid; idx < 64 * 32; idx += 256) {
            int r = idx >> 5, c4 = (idx & 31) * 4;
            *(uint4*)(Ks + r * ALDQ + c4) =
                *(const uint4*)(kvup + (tok0 + k0tok + r) * DMODEL + h * DHD + c4);
        }
        for (int idx = tid; idx < 64 * 16; idx += 256) {
            int r = idx >> 4, c4 = (idx & 15) * 4;
            *(uint4*)(Ks + r * ALDQ + 128 + c4) =
                *(const uint4*)(kr + (tok0 + k0tok + r) * (NH * DRP) + h * DRP + c4);
        }
        __syncthreads();

        float s[8][4];
        #pragma unroll
        for (int j = 0; j < 8; ++j)
            #pragma unroll
            for (int c = 0; c < 4; ++c) s[j][c] = 0.f;

        #pragma unroll 4
        for (int ks = 0; ks < 24; ++ks) {
            const int k0 = ks * 8;
            const uint32_t* abase = Qs + (wq + gr) * ALDQ + k0 + gc;
            uint32_t a0 = abase[0];
            uint32_t a2 = abase[4];
            uint32_t a1 = abase[8 * ALDQ];
            uint32_t a3 = abase[8 * ALDQ + 4];
            #pragma unroll
            for (int j = 0; j < 8; ++j) {
                const uint32_t* bbase = Ks + (8*j + gr) * ALDQ + k0 + gc;
                uint32_t b0 = bbase[0];
                uint32_t b1 = bbase[4];
                MMA_TF32(s[j][0], s[j][1], s[j][2], s[j][3], a0, a1, a2, a3, b0, b1);
            }
        }

        float mx0 = -INFINITY, mx1 = -INFINITY;
        #pragma unroll
        for (int j = 0; j < 8; ++j) {
            s[j][0] *= scale; s[j][1] *= scale; s[j][2] *= scale; s[j][3] *= scale;
            mx0 = fmaxf(mx0, fmaxf(s[j][0], s[j][1]));
            mx1 = fmaxf(mx1, fmaxf(s[j][2], s[j][3]));
        }
        #pragma unroll
        for (int off = 1; off <= 2; off <<= 1) {
            mx0 = fmaxf(mx0, __shfl_xor_sync(0xffffffffu, mx0, off));
            mx1 = fmaxf(mx1, __shfl_xor_sync(0xffffffffu, mx1, off));
        }
        float m0n = fmaxf(m0, mx0);
        float m1n = fmaxf(m1, mx1);
        float al0 = __expf(m0 - m0n);
        float al1 = __expf(m1 - m1n);
        float rs0 = 0.f, rs1 = 0.f;
        uint32_t* prow0 = Ps + (wq + gr) * ALDP;
        uint32_t* prow1 = Ps + (wq + gr + 8) * ALDP;
        #pragma unroll
        for (int j = 0; j < 8; ++j) {
            float p0 = __expf(s[j][0] - m0n);
            float p1 = __expf(s[j][1] - m0n);
            float p2 = __expf(s[j][2] - m1n);
            float p3 = __expf(s[j][3] - m1n);
            rs0 += p0 + p1; rs1 += p2 + p3;
            int c = 8*j + 2*gc;
            prow0[c]     = f2tf32(p0);
            prow0[c + 1] = f2tf32(p1);
            prow1[c]     = f2tf32(p2);
            prow1[c + 1] = f2tf32(p3);
        }
        #pragma unroll
        for (int off = 1; off <= 2; off <<= 1) {
            rs0 += __shfl_xor_sync(0xffffffffu, rs0, off);
            rs1 += __shfl_xor_sync(0xffffffffu, rs1, off);
        }
        l0 = l0 * al0 + rs0;
        l1 = l1 * al1 + rs1;
        m0 = m0n; m1 = m1n;
        #pragma unroll
        for (int j = 0; j < 16; ++j) {
            o[j][0] *= al0; o[j][1] *= al0;
            o[j][2] *= al1; o[j][3] *= al1;
        }
        __syncwarp();

        #pragma unroll 2
        for (int ks = 0; ks < 8; ++ks) {
            const int k0 = ks * 8;
            const uint32_t* pbase = Ps + (wq + gr) * ALDP + k0 + gc;
            uint32_t a0 = pbase[0];
            uint32_t a2 = pbase[4];
            uint32_t a1 = pbase[8 * ALDP];
            uint32_t a3 = pbase[8 * ALDP + 4];
            #pragma unroll
            for (int j = 0; j < 16; ++j) {
                uint32_t b0 = Ks[(k0 + gc) * ALDQ + 8*j + gr];
                uint32_t b1 = Ks[(k0 + gc + 4) * ALDQ + 8*j + gr];
                MMA_TF32(o[j][0], o[j][1], o[j][2], o[j][3], a0, a1, a2, a3, b0, b1);
            }
        }
        __syncwarp();
    }

    float inv0 = 1.0f / l0;
    float inv1 = 1.0f / l1;
    size_t r0 = (tok0 + q0 + wq + gr) * DMODEL + h * DHD;
    size_t r1 = (tok0 + q0 + wq + gr + 8) * DMODEL + h * DHD;
    #pragma unroll
    for (int j = 0; j < 16; ++j) {
        int c = 8*j + 2*gc;
        *(float2*)(out + r0 + c) =
            make_float2(roundtf(o[j][0] * inv0), roundtf(o[j][1] * inv0));
        *(float2*)(out + r1 + c) =
            make_float2(roundtf(o[j][2] * inv1), roundtf(o[j][3] * inv1));
    }
}

// ================= host launch =================
static inline void launch_gemm(const float* A, const float* Bt, const float* bias,
                               float* C, int M, int N, int K, int round_out)
{
    dim3 grid(N / GBN, M / GBM);
    gemm_cp<<<grid, 256, GEMM_SMEM>>>(A, Bt, bias, C, M, N, K, round_out);
}
static inline void launch_transpose(const float* in, float* out, int K, int N)
{
    transpose32<<<dim3(N / 32, K / 32), dim3(32, 8)>>>(in, out, K, N);
}

extern "C" void kernel_launch(void* const* d_in, const int* in_sizes, int n_in,
                              void* d_out, int out_size)
{
    (void)in_sizes; (void)n_in; (void)out_size;
    const float* x   = (const float*)d_in[0];
    const float* Wd  = (const float*)d_in[1];
    const float* bd  = (const float*)d_in[2];
    const float* Wu  = (const float*)d_in[3];
    const float* bu  = (const float*)d_in[4];
    const float* Wqd = (const float*)d_in[5];
    const float* bqd = (const float*)d_in[6];
    const float* Wqu = (const float*)d_in[7];
    const float* bqu = (const float*)d_in[8];
    const float* Wqr = (const float*)d_in[9];
    const float* bqr = (const float*)d_in[10];
    const float* Wkr = (const float*)d_in[11];
    const float* bkr = (const float*)d_in[12];
    const float* Wo  = (const float*)d_in[13];
    const float* bo  = (const float*)d_in[14];
    float* out = (float*)d_out;

    float *xt, *kvc, *kvup, *qcmp, *qcb, *qrb, *krb, *attn;
    float *wdT, *wuT, *wqdT, *wquT, *wqrT, *wkrT, *woT;
    cudaGetSymbolAddress((void**)&xt,   g_xt);
    cudaGetSymbolAddress((void**)&kvc,  g_kvc);
    cudaGetSymbolAddress((void**)&kvup, g_kvup);
    cudaGetSymbolAddress((void**)&qcmp, g_qcmp);
    cudaGetSymbolAddress((void**)&qcb,  g_qc);
    cudaGetSymbolAddress((void**)&qrb,  g_qr);
    cudaGetSymbolAddress((void**)&krb,  g_kr);
    cudaGetSymbolAddress((void**)&attn, g_attn);
    cudaGetSymbolAddress((void**)&wdT,  g_wdT);
    cudaGetSymbolAddress((void**)&wuT,  g_wuT);
    cudaGetSymbolAddress((void**)&wqdT, g_wqdT);
    cudaGetSymbolAddress((void**)&wquT, g_wquT);
    cudaGetSymbolAddress((void**)&wqrT, g_wqrT);
    cudaGetSymbolAddress((void**)&wkrT, g_wkrT);
    cudaGetSymbolAddress((void**)&woT,  g_woT);

    cudaFuncSetAttribute(gemm_cp, cudaFuncAttributeMaxDynamicSharedMemorySize,
                         GEMM_SMEM);
    cudaFuncSetAttribute(flash_mma, cudaFuncAttributeMaxDynamicSharedMemorySize,
                         FL_SMEM);

    // Launch order arranged so ncu (-s 5 -c 1) captures the first big GEMM.
    round_tf32_kernel<<<(NTOK*DMODEL/4 + 255)/256, 256>>>(x, xt, NTOK*DMODEL/4);  // L0
    launch_transpose(Wd,  wdT,  DMODEL, DC);       // L1
    launch_transpose(Wqd, wqdT, DMODEL, DCOMP);    // L2
    launch_transpose(Wkr, wkrT, DMODEL, NH*DRP);   // L3
    launch_transpose(Wu,  wuT,  DC,     DMODEL);   // L4

    launch_gemm(xt,   wdT,  bd,  kvc,  NTOK, DC,     DMODEL, 1);   // L5 (profiled)
    launch_gemm(xt,   wqdT, bqd, qcmp, NTOK, DCOMP,  DMODEL, 1);   // L6
    launch_gemm(xt,   wkrT, bkr, krb,  NTOK, NH*DRP, DMODEL, 0);   // L7
    launch_gemm(kvc,  wuT,  bu,  kvup, NTOK, DMODEL, DC,     1);   // L8

    launch_transpose(Wqu, wquT, DCOMP,  DMODEL);   // L9
    launch_transpose(Wqr, wqrT, DCOMP,  NH*DRP);   // L10
    launch_transpose(Wo,  woT,  DMODEL, DMODEL);   // L11

    launch_gemm(qcmp, wquT, bqu, qcb,  NTOK, DMODEL, DCOMP,  1);   // L12
    launch_gemm(qcmp, wqrT, bqr, qrb,  NTOK, NH*DRP, DCOMP,  0);   // L13

    {
        int n = NTOK * NH * 32;
        int blocks = (n + 255) / 256;
        rope_kernel<<<blocks, 256>>>(qrb, n);      // L14
        rope_kernel<<<blocks, 256>>>(krb, n);      // L15
    }

    {
        dim3 grid(SS / 128, NH, BB);
        flash_mma<<<grid, 256, FL_SMEM>>>(qcb, qrb, kvup, krb, attn);  // L16
    }

    launch_gemm(attn, woT, bo, out, NTOK, DMODEL, DMODEL, 0);      // L17
}

// round 7
// speedup vs baseline: 2.8676x; 1.0069x over previous
#include <cuda_runtime.h>
#include <math.h>
#include <stdint.h>

#define BB 2
#define SS 2048
#define NH 16
#define DHD 128
#define DRP 64
#define DMODEL 2048
#define DC 512
#define DCOMP 768
#define NTOK (BB*SS)

#define N1 (DCOMP + NH*DRP)          // 1792  (q_cmp | k_r)
#define N2 (DMODEL + NH*DRP)         // 3072  (q_c | q_r)
#define QR_OFF DMODEL                // q_r col offset in big2
#define KR_OFF DCOMP                 // k_r col offset in big1

// ---------------- scratch (static device globals; no allocation) ----------------
__device__ float g_xt  [NTOK*DMODEL];
__device__ float g_kvc [NTOK*DC];
__device__ float g_kvup[NTOK*DMODEL];
__device__ float g_big1[NTOK*N1];      // [4096][1792] : q_cmp | k_r
__device__ float g_big2[NTOK*N2];      // [4096][3072] : q_c | q_r
__device__ float g_attn[NTOK*DMODEL];
__device__ float g_wdT [DC*DMODEL];
__device__ float g_wuT [DMODEL*DC];
__device__ float g_bt1 [N1*DMODEL];    // Wqd^T rows 0..767 | Wkr^T rows 768..1791
__device__ float g_bt2 [N2*DCOMP];     // Wqu^T rows 0..2047 | Wqr^T rows 2048..3071
__device__ float g_woT [DMODEL*DMODEL];
__device__ float g_bias1[N1];
__device__ float g_bias2[N2];

__device__ __forceinline__ uint32_t f2tf32(float x) {
    uint32_t r;
    asm("cvt.rna.tf32.f32 %0, %1;" : "=r"(r) : "f"(x));
    return r;
}
__device__ __forceinline__ float roundtf(float x) {
    return __uint_as_float(f2tf32(x));
}
__device__ __forceinline__ uint32_t smem_u32(const void* p) {
    uint32_t a;
    asm("{ .reg .u64 t; cvta.to.shared.u64 t, %1; cvt.u32.u64 %0, t; }"
        : "=r"(a) : "l"(p));
    return a;
}

#define MMA_TF32(d0,d1,d2,d3, a0,a1,a2,a3, b0,b1) \
    asm volatile( \
        "mma.sync.aligned.m16n8k8.row.col.f32.tf32.tf32.f32 " \
        "{%0,%1,%2,%3}, {%4,%5,%6,%7}, {%8,%9}, {%0,%1,%2,%3};" \
        : "+f"(d0), "+f"(d1), "+f"(d2), "+f"(d3) \
        : "r"(a0), "r"(a1), "r"(a2), "r"(a3), "r"(b0), "r"(b1))

#define CP_ASYNC16(dst, src) \
    asm volatile("cp.async.cg.shared.global [%0], [%1], 16;" \
                 :: "r"(dst), "l"(src))
#define CP_COMMIT() asm volatile("cp.async.commit_group;" ::: "memory")
#define CP_WAIT1()  asm volatile("cp.async.wait_group 1;" ::: "memory")

// ================= helpers =================
__global__ void round_tf32_kernel(const float* __restrict__ in,
                                  float* __restrict__ out, int n4)
{
    int i = blockIdx.x * blockDim.x + threadIdx.x;
    if (i >= n4) return;
    float4 v = ((const float4*)in)[i];
    v.x = roundtf(v.x); v.y = roundtf(v.y);
    v.z = roundtf(v.z); v.w = roundtf(v.w);
    ((float4*)out)[i] = v;
}

__global__ void concat_bias(float* __restrict__ dst,
                            const float* __restrict__ a, int na,
                            const float* __restrict__ b, int nb)
{
    int i = blockIdx.x * blockDim.x + threadIdx.x;
    if (i < na) dst[i] = a[i];
    else if (i < na + nb) dst[i] = b[i - na];
}

__global__ void transpose32(const float* __restrict__ in, float* __restrict__ out,
                            int K, int N)
{
    __shared__ float t[32][33];
    int n0 = blockIdx.x * 32, k0 = blockIdx.y * 32;
    int tx = threadIdx.x, ty = threadIdx.y;  // (32, 8)
    #pragma unroll
    for (int i = 0; i < 4; ++i)
        t[ty + 8*i][tx] = in[(size_t)(k0 + ty + 8*i) * N + n0 + tx];
    __syncthreads();
    #pragma unroll
    for (int i = 0; i < 4; ++i)
        out[(size_t)(n0 + ty + 8*i) * K + k0 + tx] = roundtf(t[tx][ty + 8*i]);
}

// ================= cp.async 3-stage tf32 GEMM, 2 CTAs/SM ==================
// C[M,N] = A[M,K] @ Bt[N,K]^T + bias. A rows stride lda, C rows stride ldc.
// CTA 128x128, BK=16, 3 stages, 256 threads = 8 warps (2x4), warp tile 64x32.
#define GBK 16
#define GSTG 3
#define GLDW 20
#define GSTG_WORDS (256 * GLDW)              // 5120 words per stage
#define GEMM_SMEM (GSTG * GSTG_WORDS * 4)    // 61,440 B -> 2 CTAs/SM

__global__ __launch_bounds__(256, 2) void gemm_cp(
    const float* __restrict__ A, int lda,
    const float* __restrict__ Bt,
    const float* __restrict__ bias,
    float* __restrict__ C, int ldc,
    int N, int K, int round_out)
{
    extern __shared__ uint32_t gsm[];
    const int tid  = threadIdx.x;
    const int wid  = tid >> 5;
    const int lane = tid & 31;
    const int wm = wid >> 2, wn = wid & 3;
    const int gr = lane >> 2, gc = lane & 3;
    const int wr = wm * 64,  wc = wn * 32;

    const int row0 = blockIdx.y * 128;
    const int col0 = blockIdx.x * 128;
    const float* Ag = A  + (size_t)row0 * lda;
    const float* Bg = Bt + (size_t)col0 * K;

    // cp.async: 128 rows x 4 float4 per matrix; 256 threads -> 2 each per matrix
    const int crow = tid >> 2;          // 0..63
    const int ccol = (tid & 3) * 4;     // 0,4,8,12
    const uint32_t smbase = smem_u32(gsm);

    const int niter = K / GBK;

    auto issue_stage = [&](int it) {
        const int s = it % GSTG;
        const int ko = it * GBK;
        uint32_t as = smbase + (uint32_t)(s * GSTG_WORDS) * 4u;
        uint32_t bs = as + (uint32_t)(128 * GLDW) * 4u;
        #pragma unroll
        for (int c = 0; c < 2; ++c) {
            int r = crow + 64 * c;
            CP_ASYNC16(as + (uint32_t)(r * GLDW + ccol) * 4u,
                       Ag + (size_t)r * lda + ko + ccol);
            CP_ASYNC16(bs + (uint32_t)(r * GLDW + ccol) * 4u,
                       Bg + (size_t)r * K + ko + ccol);
        }
    };

    float acc[4][4][4];
    #pragma unroll
    for (int i = 0; i < 4; ++i)
        #pragma unroll
        for (int j = 0; j < 4; ++j)
            #pragma unroll
            for (int c = 0; c < 4; ++c) acc[i][j][c] = 0.f;

    issue_stage(0); CP_COMMIT();
    issue_stage(1); CP_COMMIT();

    for (int it = 0; it < niter; ++it) {
        CP_WAIT1();
        __syncthreads();

        if (it + 2 < niter) issue_stage(it + 2);
        CP_COMMIT();

        const uint32_t* As = gsm + (it % GSTG) * GSTG_WORDS;
        const uint32_t* Bs = As + 128 * GLDW;

        #pragma unroll
        for (int ks = 0; ks < 2; ++ks) {
            const int k0 = ks * 8;
            uint32_t a[4][4], b[4][2];
            #pragma unroll
            for (int i = 0; i < 4; ++i) {
                const uint32_t* base = As + (wr + 16*i + gr) * GLDW + k0 + gc;
                a[i][0] = base[0];
                a[i][2] = base[4];
                a[i][1] = base[8 * GLDW];
                a[i][3] = base[8 * GLDW + 4];
            }
            #pragma unroll
            for (int j = 0; j < 4; ++j) {
                const uint32_t* base = Bs + (wc + 8*j + gr) * GLDW + k0 + gc;
                b[j][0] = base[0];
                b[j][1] = base[4];
            }
            #pragma unroll
            for (int i = 0; i < 4; ++i)
                #pragma unroll
                for (int j = 0; j < 4; ++j)
                    MMA_TF32(acc[i][j][0], acc[i][j][1], acc[i][j][2], acc[i][j][3],
                             a[i][0], a[i][1], a[i][2], a[i][3], b[j][0], b[j][1]);
        }
    }

    #pragma unroll
    for (int j = 0; j < 4; ++j) {
        int c = col0 + wc + 8*j + 2*gc;
        float bv0 = bias[c], bv1 = bias[c + 1];
        #pragma unroll
        for (int i = 0; i < 4; ++i) {
            int r = row0 + wr + 16*i + gr;
            float f0 = acc[i][j][0] + bv0, f1 = acc[i][j][1] + bv1;
            float f2 = acc[i][j][2] + bv0, f3 = acc[i][j][3] + bv1;
            if (round_out) {
                f0 = roundtf(f0); f1 = roundtf(f1);
                f2 = roundtf(f2); f3 = roundtf(f3);
            }
            *(float2*)(C + (size_t)r * ldc + c)       = make_float2(f0, f1);
            *(float2*)(C + (size_t)(r + 8) * ldc + c) = make_float2(f2, f3);
        }
    }
}

// ================= RoPE (in place on a column slice), rounds to tf32 ==========
__global__ void rope_kernel(float* __restrict__ buf, int ld, int off, int n)
{
    int idx = blockIdx.x * blockDim.x + threadIdx.x;
    if (idx >= n) return;
    int i = idx & 31;
    int h = (idx >> 5) & (NH - 1);
    int t = idx >> 9;
    int pos = t & (SS - 1);

    float freq = exp2f(-13.287712379549449f * (float)i / 32.0f);
    float ang = (float)pos * freq;
    float sn, cs;
    sincosf(ang, &sn, &cs);

    float* p = buf + (size_t)t * ld + off + h * DRP + 2 * i;
    float x1 = p[0], x2 = p[1];
    p[0] = roundtf(x1 * cs - x2 * sn);
    p[1] = roundtf(x1 * sn + x2 * cs);
}

// ================= flash attention with tf32 mma.sync =================
#define ALDQ 196
#define ALDP 68
#define FL_SMEM ((128*ALDQ + 64*ALDQ + 128*ALDP) * 4)   // 185,344 B

__global__ __launch_bounds__(256, 1) void flash_mma(
    const float* __restrict__ qcr,    // big2: q_c cols [0,2048), q_r at QR_OFF
    const float* __restrict__ kvup,   // [4096][2048]
    const float* __restrict__ krb,    // big1: k_r at KR_OFF, ld N1
    float* __restrict__ out)
{
    extern __shared__ uint32_t sm[];
    uint32_t* Qs = sm;                       // [128][196]
    uint32_t* Ks = sm + 128 * ALDQ;          // [64][196]
    uint32_t* Ps = Ks + 64 * ALDQ;           // [128][68]

    const int tid  = threadIdx.x;
    const int wid  = tid >> 5;
    const int lane = tid & 31;
    const int gr = lane >> 2;
    const int gc = lane & 3;
    const int wq = wid * 16;

    const int q0 = blockIdx.x * 128;
    const int h  = blockIdx.y;
    const int b  = blockIdx.z;
    const size_t tok0 = (size_t)b * SS;

    for (int idx = tid; idx < 128 * 32; idx += 256) {
        int r = idx >> 5, c4 = (idx & 31) * 4;
        *(uint4*)(Qs + r * ALDQ + c4) =
            *(const uint4*)(qcr + (tok0 + q0 + r) * N2 + h * DHD + c4);
    }
    for (int idx = tid; idx < 128 * 16; idx += 256) {
        int r = idx >> 4, c4 = (idx & 15) * 4;
        *(uint4*)(Qs + r * ALDQ + 128 + c4) =
            *(const uint4*)(qcr + (tok0 + q0 + r) * N2 + QR_OFF + h * DRP + c4);
    }

    float m0 = -INFINITY, m1 = -INFINITY, l0 = 0.f, l1 = 0.f;
    float o[16][4];
    #pragma unroll
    for (int j = 0; j < 16; ++j)
        #pragma unroll
        for (int c = 0; c < 4; ++c) o[j][c] = 0.f;

    const float scale = 0.08838834764831845f;  // 1/sqrt(128)

    for (int kt = 0; kt < SS / 64; ++kt) {
        const int k0tok = kt * 64;
        __syncthreads();
        for (int idx = tid; idx < 64 * 32; idx += 256) {
            int r = idx >> 5, c4 = (idx & 31) * 4;
            *(uint4*)(Ks + r * ALDQ + c4) =
                *(const uint4*)(kvup + (tok0 + k0tok + r) * DMODEL + h * DHD + c4);
        }
        for (int idx = tid; idx < 64 * 16; idx += 256) {
            int r = idx >> 4, c4 = (idx & 15) * 4;
            *(uint4*)(Ks + r * ALDQ + 128 + c4) =
                *(const uint4*)(krb + (tok0 + k0tok + r) * N1 + KR_OFF + h * DRP + c4);
        }
        __syncthreads();

        float s[8][4];
        #pragma unroll
        for (int j = 0; j < 8; ++j)
            #pragma unroll
            for (int c = 0; c < 4; ++c) s[j][c] = 0.f;

        #pragma unroll 4
        for (int ks = 0; ks < 24; ++ks) {
            const int k0 = ks * 8;
            const uint32_t* abase = Qs + (wq + gr) * ALDQ + k0 + gc;
            uint32_t a0 = abase[0];
            uint32_t a2 = abase[4];
            uint32_t a1 = abase[8 * ALDQ];
            uint32_t a3 = abase[8 * ALDQ + 4];
            #pragma unroll
            for (int j = 0; j < 8; ++j) {
                const uint32_t* bbase = Ks + (8*j + gr) * ALDQ + k0 + gc;
                uint32_t b0 = bbase[0];
                uint32_t b1 = bbase[4];
                MMA_TF32(s[j][0], s[j][1], s[j][2], s[j][3], a0, a1, a2, a3, b0, b1);
            }
        }

        float mx0 = -INFINITY, mx1 = -INFINITY;
        #pragma unroll
        for (int j = 0; j < 8; ++j) {
            s[j][0] *= scale; s[j][1] *= scale; s[j][2] *= scale; s[j][3] *= scale;
            mx0 = fmaxf(mx0, fmaxf(s[j][0], s[j][1]));
            mx1 = fmaxf(mx1, fmaxf(s[j][2], s[j][3]));
        }
        #pragma unroll
        for (int off = 1; off <= 2; off <<= 1) {
            mx0 = fmaxf(mx0, __shfl_xor_sync(0xffffffffu, mx0, off));
            mx1 = fmaxf(mx1, __shfl_xor_sync(0xffffffffu, mx1, off));
        }
        float m0n = fmaxf(m0, mx0);
        float m1n = fmaxf(m1, mx1);
        float al0 = __expf(m0 - m0n);
        float al1 = __expf(m1 - m1n);
        float rs0 = 0.f, rs1 = 0.f;
        uint32_t* prow0 = Ps + (wq + gr) * ALDP;
        uint32_t* prow1 = Ps + (wq + gr + 8) * ALDP;
        #pragma unroll
        for (int j = 0; j < 8; ++j) {
            float p0 = __expf(s[j][0] - m0n);
            float p1 = __expf(s[j][1] - m0n);
            float p2 = __expf(s[j][2] - m1n);
            float p3 = __expf(s[j][3] - m1n);
            rs0 += p0 + p1; rs1 += p2 + p3;
            int c = 8*j + 2*gc;
            prow0[c]     = f2tf32(p0);
            prow0[c + 1] = f2tf32(p1);
            prow1[c]     = f2tf32(p2);
            prow1[c + 1] = f2tf32(p3);
        }
        #pragma unroll
        for (int off = 1; off <= 2; off <<= 1) {
            rs0 += __shfl_xor_sync(0xffffffffu, rs0, off);
            rs1 += __shfl_xor_sync(0xffffffffu, rs1, off);
        }
        l0 = l0 * al0 + rs0;
        l1 = l1 * al1 + rs1;
        m0 = m0n; m1 = m1n;
        #pragma unroll
        for (int j = 0; j < 16; ++j) {
            o[j][0] *= al0; o[j][1] *= al0;
            o[j][2] *= al1; o[j][3] *= al1;
        }
        __syncwarp();

        #pragma unroll 2
        for (int ks = 0; ks < 8; ++ks) {
            const int k0 = ks * 8;
            const uint32_t* pbase = Ps + (wq + gr) * ALDP + k0 + gc;
            uint32_t a0 = pbase[0];
            uint32_t a2 = pbase[4];
            uint32_t a1 = pbase[8 * ALDP];
            uint32_t a3 = pbase[8 * ALDP + 4];
            #pragma unroll
            for (int j = 0; j < 16; ++j) {
                uint32_t b0 = Ks[(k0 + gc) * ALDQ + 8*j + gr];
                uint32_t b1 = Ks[(k0 + gc + 4) * ALDQ + 8*j + gr];
                MMA_TF32(o[j][0], o[j][1], o[j][2], o[j][3], a0, a1, a2, a3, b0, b1);
            }
        }
        __syncwarp();
    }

    float inv0 = 1.0f / l0;
    float inv1 = 1.0f / l1;
    size_t r0 = (tok0 + q0 + wq + gr) * DMODEL + h * DHD;
    size_t r1 = (tok0 + q0 + wq + gr + 8) * DMODEL + h * DHD;
    #pragma unroll
    for (int j = 0; j < 16; ++j) {
        int c = 8*j + 2*gc;
        *(float2*)(out + r0 + c) =
            make_float2(roundtf(o[j][0] * inv0), roundtf(o[j][1] * inv0));
        *(float2*)(out + r1 + c) =
            make_float2(roundtf(o[j][2] * inv1), roundtf(o[j][3] * inv1));
    }
}

// ================= host launch =================
static inline void launch_gemm(const float* A, int lda, const float* Bt,
                               const float* bias, float* C, int ldc,
                               int N, int K, int round_out)
{
    dim3 grid(N / 128, NTOK / 128);
    gemm_cp<<<grid, 256, GEMM_SMEM>>>(A, lda, Bt, bias, C, ldc, N, K, round_out);
}
static inline void launch_transpose(const float* in, float* out, int K, int N)
{
    transpose32<<<dim3(N / 32, K / 32), dim3(32, 8)>>>(in, out, K, N);
}

extern "C" void kernel_launch(void* const* d_in, const int* in_sizes, int n_in,
                              void* d_out, int out_size)
{
    (void)in_sizes; (void)n_in; (void)out_size;
    const float* x   = (const float*)d_in[0];
    const float* Wd  = (const float*)d_in[1];
    const float* bd  = (const float*)d_in[2];
    const float* Wu  = (const float*)d_in[3];
    const float* bu  = (const float*)d_in[4];
    const float* Wqd = (const float*)d_in[5];
    const float* bqd = (const float*)d_in[6];
    const float* Wqu = (const float*)d_in[7];
    const float* bqu = (const float*)d_in[8];
    const float* Wqr = (const float*)d_in[9];
    const float* bqr = (const float*)d_in[10];
    const float* Wkr = (const float*)d_in[11];
    const float* bkr = (const float*)d_in[12];
    const float* Wo  = (const float*)d_in[13];
    const float* bo  = (const float*)d_in[14];
    float* out = (float*)d_out;

    float *xt, *kvc, *kvup, *big1, *big2, *attn;
    float *wdT, *wuT, *bt1, *bt2, *woT, *bias1, *bias2;
    cudaGetSymbolAddress((void**)&xt,    g_xt);
    cudaGetSymbolAddress((void**)&kvc,   g_kvc);
    cudaGetSymbolAddress((void**)&kvup,  g_kvup);
    cudaGetSymbolAddress((void**)&big1,  g_big1);
    cudaGetSymbolAddress((void**)&big2,  g_big2);
    cudaGetSymbolAddress((void**)&attn,  g_attn);
    cudaGetSymbolAddress((void**)&wdT,   g_wdT);
    cudaGetSymbolAddress((void**)&wuT,   g_wuT);
    cudaGetSymbolAddress((void**)&bt1,   g_bt1);
    cudaGetSymbolAddress((void**)&bt2,   g_bt2);
    cudaGetSymbolAddress((void**)&woT,   g_woT);
    cudaGetSymbolAddress((void**)&bias1, g_bias1);
    cudaGetSymbolAddress((void**)&bias2, g_bias2);

    cudaFuncSetAttribute(gemm_cp, cudaFuncAttributeMaxDynamicSharedMemorySize,
                         GEMM_SMEM);
    cudaFuncSetAttribute(flash_mma, cudaFuncAttributeMaxDynamicSharedMemorySize,
                         FL_SMEM);

    // L0: pre-round x
    round_tf32_kernel<<<(NTOK*DMODEL/4 + 255)/256, 256>>>(x, xt, NTOK*DMODEL/4);
    // L1, L2: transposes needed so L3 is a GEMM (profiled launch index = 3)
    launch_transpose(Wd,  wdT, DMODEL, DC);                       // L1
    launch_transpose(Wqd, bt1, DMODEL, DCOMP);                    // L2 -> bt1 rows 0..767
    // L3: kv_c GEMM  <-- PROFILED
    launch_gemm(xt, DMODEL, wdT, bd, kvc, DC, DC, DMODEL, 1);     // L3
    launch_transpose(Wkr, bt1 + (size_t)DCOMP * DMODEL, DMODEL, NH*DRP);  // L4
    concat_bias<<<(N1 + 255)/256, 256>>>(bias1, bqd, DCOMP, bkr, NH*DRP); // L5
    // L6: fused (q_cmp | k_r) GEMM
    launch_gemm(xt, DMODEL, bt1, bias1, big1, N1, N1, DMODEL, 1); // L6
    launch_transpose(Wu, wuT, DC, DMODEL);                        // L7
    // L8: kv_up GEMM
    launch_gemm(kvc, DC, wuT, bu, kvup, DMODEL, DMODEL, DC, 1);   // L8
    launch_transpose(Wqu, bt2, DCOMP, DMODEL);                    // L9
    launch_transpose(Wqr, bt2 + (size_t)DMODEL * DCOMP, DCOMP, NH*DRP);   // L10
    concat_bias<<<(N2 + 255)/256, 256>>>(bias2, bqu, DMODEL, bqr, NH*DRP);// L11
    // L12: fused (q_c | q_r) GEMM ; A = q_cmp = big1 cols [0,768)
    launch_gemm(big1, N1, bt2, bias2, big2, N2, N2, DCOMP, 1);    // L12

    {
        int n = NTOK * NH * 32;
        int blocks = (n + 255) / 256;
        rope_kernel<<<blocks, 256>>>(big2, N2, QR_OFF, n);        // L13 (q_r)
        rope_kernel<<<blocks, 256>>>(big1, N1, KR_OFF, n);        // L14 (k_r)
    }

    launch_transpose(Wo, woT, DMODEL, DMODEL);                    // L15

    {
        dim3 grid(SS / 128, NH, BB);
        flash_mma<<<grid, 256, FL_SMEM>>>(big2, kvup, big1, attn);// L16
    }

    // L17: output projection (full fp32 output)
    launch_gemm(attn, DMODEL, woT, bo, out, DMODEL, DMODEL, DMODEL, 0);
}

// round 8
// speedup vs baseline: 3.0716x; 1.0711x over previous
#include <cuda_runtime.h>
#include <math.h>
#include <stdint.h>

#define BB 2
#define SS 2048
#define NH 16
#define DHD 128
#define DRP 64
#define DMODEL 2048
#define DC 512
#define DCOMP 768
#define NTOK (BB*SS)

#define N0 (DC + DCOMP + NH*DRP)     // 2304  (kv_c | q_cmp | k_r)
#define QCMP_OFF DC                  // 512
#define KR_OFF0 (DC + DCOMP)         // 1280
#define N2 (DMODEL + NH*DRP)         // 3072  (q_c | q_r)
#define QR_OFF DMODEL                // 2048

// ---------------- scratch (static device globals; no allocation) ----------------
__device__ float g_xt  [NTOK*DMODEL];
__device__ float g_big0[NTOK*N0];      // [4096][2304] : kv_c | q_cmp | k_r
__device__ float g_kvup[NTOK*DMODEL];
__device__ float g_big2[NTOK*N2];      // [4096][3072] : q_c | q_r
__device__ float g_attn[NTOK*DMODEL];
__device__ float g_bt0 [N0*DMODEL];    // [Wd|Wqd|Wkr]^T
__device__ float g_wuT [DMODEL*DC];
__device__ float g_bt2 [N2*DCOMP];     // [Wqu|Wqr]^T
__device__ float g_woT [DMODEL*DMODEL];
__device__ float g_bias0[N0];
__device__ float g_bias2[N2];

__device__ __forceinline__ uint32_t f2tf32(float x) {
    uint32_t r;
    asm("cvt.rna.tf32.f32 %0, %1;" : "=r"(r) : "f"(x));
    return r;
}
__device__ __forceinline__ float roundtf(float x) {
    return __uint_as_float(f2tf32(x));
}
__device__ __forceinline__ uint32_t smem_u32(const void* p) {
    uint32_t a;
    asm("{ .reg .u64 t; cvta.to.shared.u64 t, %1; cvt.u32.u64 %0, t; }"
        : "=r"(a) : "l"(p));
    return a;
}

#define MMA_TF32(d0,d1,d2,d3, a0,a1,a2,a3, b0,b1) \
    asm volatile( \
        "mma.sync.aligned.m16n8k8.row.col.f32.tf32.tf32.f32 " \
        "{%0,%1,%2,%3}, {%4,%5,%6,%7}, {%8,%9}, {%0,%1,%2,%3};" \
        : "+f"(d0), "+f"(d1), "+f"(d2), "+f"(d3) \
        : "r"(a0), "r"(a1), "r"(a2), "r"(a3), "r"(b0), "r"(b1))

#define CP_ASYNC16(dst, src) \
    asm volatile("cp.async.cg.shared.global [%0], [%1], 16;" \
                 :: "r"(dst), "l"(src))
#define CP_COMMIT() asm volatile("cp.async.commit_group;" ::: "memory")
#define CP_WAIT1()  asm volatile("cp.async.wait_group 1;" ::: "memory")

// ================= helpers =================
__global__ void round_tf32_kernel(const float* __restrict__ in,
                                  float* __restrict__ out, int n4)
{
    int i = blockIdx.x * blockDim.x + threadIdx.x;
    if (i >= n4) return;
    float4 v = ((const float4*)in)[i];
    v.x = roundtf(v.x); v.y = roundtf(v.y);
    v.z = roundtf(v.z); v.w = roundtf(v.w);
    ((float4*)out)[i] = v;
}

__global__ void concat_bias3(float* __restrict__ dst,
                             const float* __restrict__ a, int na,
                             const float* __restrict__ b, int nb,
                             const float* __restrict__ c, int nc)
{
    int i = blockIdx.x * blockDim.x + threadIdx.x;
    if (i < na) dst[i] = a[i];
    else if (i < na + nb) dst[i] = b[i - na];
    else if (i < na + nb + nc) dst[i] = c[i - na - nb];
}

// transpose up to 3 concatenated weight matrices (shared K) into out[n][k], tf32-rounded
__global__ void transpose_multi(
    const float* __restrict__ in0, int nsz0,
    const float* __restrict__ in1, int nsz1,
    const float* __restrict__ in2, int nsz2,
    float* __restrict__ out, int K)
{
    __shared__ float t[32][33];
    int gn = blockIdx.x * 32;    // output row base (global col across concat)
    int k0 = blockIdx.y * 32;
    const float* src; int N; int col0;
    if (gn < nsz0)              { src = in0; N = nsz0; col0 = gn; }
    else if (gn < nsz0 + nsz1)  { src = in1; N = nsz1; col0 = gn - nsz0; }
    else                        { src = in2; N = nsz2; col0 = gn - nsz0 - nsz1; }
    int tx = threadIdx.x, ty = threadIdx.y;  // (32, 8)
    #pragma unroll
    for (int i = 0; i < 4; ++i)
        t[ty + 8*i][tx] = src[(size_t)(k0 + ty + 8*i) * N + col0 + tx];
    __syncthreads();
    #pragma unroll
    for (int i = 0; i < 4; ++i)
        out[(size_t)(gn + ty + 8*i) * K + k0 + tx] = roundtf(t[tx][ty + 8*i]);
}

// ================= cp.async 3-stage tf32 GEMM, 2 CTAs/SM, BK=32 ==============
// C[M,N] = A[M,K] @ Bt[N,K]^T + bias. A rows stride lda, C rows stride ldc.
// CTA 128x128, 256 threads = 8 warps (2x4), warp tile 64x32.
#define GBK 32
#define GSTG 3
#define GLDW 36
#define GSTG_WORDS (256 * GLDW)              // 9216 words per stage
#define GEMM_SMEM (GSTG * GSTG_WORDS * 4)    // 110,592 B; x2 CTA = 221,184 <= 228K

__global__ __launch_bounds__(256, 2) void gemm_cp(
    const float* __restrict__ A, int lda,
    const float* __restrict__ Bt,
    const float* __restrict__ bias,
    float* __restrict__ C, int ldc,
    int N, int K, int round_out)
{
    extern __shared__ uint32_t gsm[];
    const int tid  = threadIdx.x;
    const int wid  = tid >> 5;
    const int lane = tid & 31;
    const int wm = wid >> 2, wn = wid & 3;
    const int gr = lane >> 2, gc = lane & 3;
    const int wr = wm * 64,  wc = wn * 32;

    const int row0 = blockIdx.y * 128;
    const int col0 = blockIdx.x * 128;
    const float* Ag = A  + (size_t)row0 * lda;
    const float* Bg = Bt + (size_t)col0 * K;

    // cp.async: 128 rows x 8 float4 per matrix; 256 threads -> 4 each per matrix
    const int crow = tid >> 3;          // 0..31
    const int ccol = (tid & 7) * 4;     // 0,4,...,28
    const uint32_t smbase = smem_u32(gsm);

    const int niter = K / GBK;

    auto issue_stage = [&](int it) {
        const int s = it % GSTG;
        const int ko = it * GBK;
        uint32_t as = smbase + (uint32_t)(s * GSTG_WORDS) * 4u;
        uint32_t bs = as + (uint32_t)(128 * GLDW) * 4u;
        #pragma unroll
        for (int c = 0; c < 4; ++c) {
            int r = crow + 32 * c;
            CP_ASYNC16(as + (uint32_t)(r * GLDW + ccol) * 4u,
                       Ag + (size_t)r * lda + ko + ccol);
            CP_ASYNC16(bs + (uint32_t)(r * GLDW + ccol) * 4u,
                       Bg + (size_t)r * K + ko + ccol);
        }
    };

    float acc[4][4][4];
    #pragma unroll
    for (int i = 0; i < 4; ++i)
        #pragma unroll
        for (int j = 0; j < 4; ++j)
            #pragma unroll
            for (int c = 0; c < 4; ++c) acc[i][j][c] = 0.f;

    issue_stage(0); CP_COMMIT();
    issue_stage(1); CP_COMMIT();

    for (int it = 0; it < niter; ++it) {
        CP_WAIT1();
        __syncthreads();

        if (it + 2 < niter) issue_stage(it + 2);
        CP_COMMIT();

        const uint32_t* As = gsm + (it % GSTG) * GSTG_WORDS;
        const uint32_t* Bs = As + 128 * GLDW;

        #pragma unroll
        for (int ks = 0; ks < 4; ++ks) {
            const int k0 = ks * 8;
            uint32_t a[4][4], b[4][2];
            #pragma unroll
            for (int i = 0; i < 4; ++i) {
                const uint32_t* base = As + (wr + 16*i + gr) * GLDW + k0 + gc;
                a[i][0] = base[0];
                a[i][2] = base[4];
                a[i][1] = base[8 * GLDW];
                a[i][3] = base[8 * GLDW + 4];
            }
            #pragma unroll
            for (int j = 0; j < 4; ++j) {
                const uint32_t* base = Bs + (wc + 8*j + gr) * GLDW + k0 + gc;
                b[j][0] = base[0];
                b[j][1] = base[4];
            }
            #pragma unroll
            for (int i = 0; i < 4; ++i)
                #pragma unroll
                for (int j = 0; j < 4; ++j)
                    MMA_TF32(acc[i][j][0], acc[i][j][1], acc[i][j][2], acc[i][j][3],
                             a[i][0], a[i][1], a[i][2], a[i][3], b[j][0], b[j][1]);
        }
    }

    #pragma unroll
    for (int j = 0; j < 4; ++j) {
        int c = col0 + wc + 8*j + 2*gc;
        float bv0 = bias[c], bv1 = bias[c + 1];
        #pragma unroll
        for (int i = 0; i < 4; ++i) {
            int r = row0 + wr + 16*i + gr;
            float f0 = acc[i][j][0] + bv0, f1 = acc[i][j][1] + bv1;
            float f2 = acc[i][j][2] + bv0, f3 = acc[i][j][3] + bv1;
            if (round_out) {
                f0 = roundtf(f0); f1 = roundtf(f1);
                f2 = roundtf(f2); f3 = roundtf(f3);
            }
            *(float2*)(C + (size_t)r * ldc + c)       = make_float2(f0, f1);
            *(float2*)(C + (size_t)(r + 8) * ldc + c) = make_float2(f2, f3);
        }
    }
}

// ================= RoPE (in place on a column slice), rounds to tf32 ==========
__global__ void rope_kernel(float* __restrict__ buf, int ld, int off, int n)
{
    int idx = blockIdx.x * blockDim.x + threadIdx.x;
    if (idx >= n) return;
    int i = idx & 31;
    int h = (idx >> 5) & (NH - 1);
    int t = idx >> 9;
    int pos = t & (SS - 1);

    float freq = exp2f(-13.287712379549449f * (float)i / 32.0f);
    float ang = (float)pos * freq;
    float sn, cs;
    sincosf(ang, &sn, &cs);

    float* p = buf + (size_t)t * ld + off + h * DRP + 2 * i;
    float x1 = p[0], x2 = p[1];
    p[0] = roundtf(x1 * cs - x2 * sn);
    p[1] = roundtf(x1 * sn + x2 * cs);
}

// ================= flash attention with tf32 mma.sync =================
#define ALDQ 196
#define ALDP 68
#define FL_SMEM ((128*ALDQ + 64*ALDQ + 128*ALDP) * 4)   // 185,344 B

__global__ __launch_bounds__(256, 1) void flash_mma(
    const float* __restrict__ qcr,    // big2: q_c cols [0,2048), q_r at QR_OFF; ld N2
    const float* __restrict__ kvup,   // [4096][2048]
    const float* __restrict__ krb,    // big0: k_r at KR_OFF0; ld N0
    float* __restrict__ out)
{
    extern __shared__ uint32_t sm[];
    uint32_t* Qs = sm;                       // [128][196]
    uint32_t* Ks = sm + 128 * ALDQ;          // [64][196]
    uint32_t* Ps = Ks + 64 * ALDQ;           // [128][68]

    const int tid  = threadIdx.x;
    const int wid  = tid >> 5;
    const int lane = tid & 31;
    const int gr = lane >> 2;
    const int gc = lane & 3;
    const int wq = wid * 16;

    const int q0 = blockIdx.x * 128;
    const int h  = blockIdx.y;
    const int b  = blockIdx.z;
    const size_t tok0 = (size_t)b * SS;

    for (int idx = tid; idx < 128 * 32; idx += 256) {
        int r = idx >> 5, c4 = (idx & 31) * 4;
        *(uint4*)(Qs + r * ALDQ + c4) =
            *(const uint4*)(qcr + (tok0 + q0 + r) * N2 + h * DHD + c4);
    }
    for (int idx = tid; idx < 128 * 16; idx += 256) {
        int r = idx >> 4, c4 = (idx & 15) * 4;
        *(uint4*)(Qs + r * ALDQ + 128 + c4) =
            *(const uint4*)(qcr + (tok0 + q0 + r) * N2 + QR_OFF + h * DRP + c4);
    }

    float m0 = -INFINITY, m1 = -INFINITY, l0 = 0.f, l1 = 0.f;
    float o[16][4];
    #pragma unroll
    for (int j = 0; j < 16; ++j)
        #pragma unroll
        for (int c = 0; c < 4; ++c) o[j][c] = 0.f;

    const float scale = 0.08838834764831845f;  // 1/sqrt(128)

    for (int kt = 0; kt < SS / 64; ++kt) {
        const int k0tok = kt * 64;
        __syncthreads();
        for (int idx = tid; idx < 64 * 32; idx += 256) {
            int r = idx >> 5, c4 = (idx & 31) * 4;
            *(uint4*)(Ks + r * ALDQ + c4) =
                *(const uint4*)(kvup + (tok0 + k0tok + r) * DMODEL + h * DHD + c4);
        }
        for (int idx = tid; idx < 64 * 16; idx += 256) {
            int r = idx >> 4, c4 = (idx & 15) * 4;
            *(uint4*)(Ks + r * ALDQ + 128 + c4) =
                *(const uint4*)(krb + (tok0 + k0tok + r) * N0 + KR_OFF0 + h * DRP + c4);
        }
        __syncthreads();

        float s[8][4];
        #pragma unroll
        for (int j = 0; j < 8; ++j)
            #pragma unroll
            for (int c = 0; c < 4; ++c) s[j][c] = 0.f;

        #pragma unroll 4
        for (int ks = 0; ks < 24; ++ks) {
            const int k0 = ks * 8;
            const uint32_t* abase = Qs + (wq + gr) * ALDQ + k0 + gc;
            uint32_t a0 = abase[0];
            uint32_t a2 = abase[4];
            uint32_t a1 = abase[8 * ALDQ];
            uint32_t a3 = abase[8 * ALDQ + 4];
            #pragma unroll
            for (int j = 0; j < 8; ++j) {
                const uint32_t* bbase = Ks + (8*j + gr) * ALDQ + k0 + gc;
                uint32_t b0 = bbase[0];
                uint32_t b1 = bbase[4];
                MMA_TF32(s[j][0], s[j][1], s[j][2], s[j][3], a0, a1, a2, a3, b0, b1);
            }
        }

        float mx0 = -INFINITY, mx1 = -INFINITY;
        #pragma unroll
        for (int j = 0; j < 8; ++j) {
            s[j][0] *= scale; s[j][1] *= scale; s[j][2] *= scale; s[j][3] *= scale;
            mx0 = fmaxf(mx0, fmaxf(s[j][0], s[j][1]));
            mx1 = fmaxf(mx1, fmaxf(s[j][2], s[j][3]));
        }
        #pragma unroll
        for (int off = 1; off <= 2; off <<= 1) {
            mx0 = fmaxf(mx0, __shfl_xor_sync(0xffffffffu, mx0, off));
            mx1 = fmaxf(mx1, __shfl_xor_sync(0xffffffffu, mx1, off));
        }
        float m0n = fmaxf(m0, mx0);
        float m1n = fmaxf(m1, mx1);
        float al0 = __expf(m0 - m0n);
        float al1 = __expf(m1 - m1n);
        float rs0 = 0.f, rs1 = 0.f;
        uint32_t* prow0 = Ps + (wq + gr) * ALDP;
        uint32_t* prow1 = Ps + (wq + gr + 8) * ALDP;
        #pragma unroll
        for (int j = 0; j < 8; ++j) {
            float p0 = __expf(s[j][0] - m0n);
            float p1 = __expf(s[j][1] - m0n);
            float p2 = __expf(s[j][2] - m1n);
            float p3 = __expf(s[j][3] - m1n);
            rs0 += p0 + p1; rs1 += p2 + p3;
            int c = 8*j + 2*gc;
            prow0[c]     = f2tf32(p0);
            prow0[c + 1] = f2tf32(p1);
            prow1[c]     = f2tf32(p2);
            prow1[c + 1] = f2tf32(p3);
        }
        #pragma unroll
        for (int off = 1; off <= 2; off <<= 1) {
            rs0 += __shfl_xor_sync(0xffffffffu, rs0, off);
            rs1 += __shfl_xor_sync(0xffffffffu, rs1, off);
        }
        l0 = l0 * al0 + rs0;
        l1 = l1 * al1 + rs1;
        m0 = m0n; m1 = m1n;
        #pragma unroll
        for (int j = 0; j < 16; ++j) {
            o[j][0] *= al0; o[j][1] *= al0;
            o[j][2] *= al1; o[j][3] *= al1;
        }
        __syncwarp();

        #pragma unroll 2
        for (int ks = 0; ks < 8; ++ks) {
            const int k0 = ks * 8;
            const uint32_t* pbase = Ps + (wq + gr) * ALDP + k0 + gc;
            uint32_t a0 = pbase[0];
            uint32_t a2 = pbase[4];
            uint32_t a1 = pbase[8 * ALDP];
            uint32_t a3 = pbase[8 * ALDP + 4];
            #pragma unroll
            for (int j = 0; j < 16; ++j) {
                uint32_t b0 = Ks[(k0 + gc) * ALDQ + 8*j + gr];
                uint32_t b1 = Ks[(k0 + gc + 4) * ALDQ + 8*j + gr];
                MMA_TF32(o[j][0], o[j][1], o[j][2], o[j][3], a0, a1, a2, a3, b0, b1);
            }
        }
        __syncwarp();
    }

    float inv0 = 1.0f / l0;
    float inv1 = 1.0f / l1;
    size_t r0 = (tok0 + q0 + wq + gr) * DMODEL + h * DHD;
    size_t r1 = (tok0 + q0 + wq + gr + 8) * DMODEL + h * DHD;
    #pragma unroll
    for (int j = 0; j < 16; ++j) {
        int c = 8*j + 2*gc;
        *(float2*)(out + r0 + c) =
            make_float2(roundtf(o[j][0] * inv0), roundtf(o[j][1] * inv0));
        *(float2*)(out + r1 + c) =
            make_float2(roundtf(o[j][2] * inv1), roundtf(o[j][3] * inv1));
    }
}

// ================= host launch =================
static inline void launch_gemm(const float* A, int lda, const float* Bt,
                               const float* bias, float* C, int ldc,
                               int N, int K, int round_out)
{
    dim3 grid(N / 128, NTOK / 128);
    gemm_cp<<<grid, 256, GEMM_SMEM>>>(A, lda, Bt, bias, C, ldc, N, K, round_out);
}

extern "C" void kernel_launch(void* const* d_in, const int* in_sizes, int n_in,
                              void* d_out, int out_size)
{
    (void)in_sizes; (void)n_in; (void)out_size;
    const float* x   = (const float*)d_in[0];
    const float* Wd  = (const float*)d_in[1];
    const float* bd  = (const float*)d_in[2];
    const float* Wu  = (const float*)d_in[3];
    const float* bu  = (const float*)d_in[4];
    const float* Wqd = (const float*)d_in[5];
    const float* bqd = (const float*)d_in[6];
    const float* Wqu = (const float*)d_in[7];
    const float* bqu = (const float*)d_in[8];
    const float* Wqr = (const float*)d_in[9];
    const float* bqr = (const float*)d_in[10];
    const float* Wkr = (const float*)d_in[11];
    const float* bkr = (const float*)d_in[12];
    const float* Wo  = (const float*)d_in[13];
    const float* bo  = (const float*)d_in[14];
    float* out = (float*)d_out;

    float *xt, *big0, *kvup, *big2, *attn;
    float *bt0, *wuT, *bt2, *woT, *bias0, *bias2;
    cudaGetSymbolAddress((void**)&xt,    g_xt);
    cudaGetSymbolAddress((void**)&big0,  g_big0);
    cudaGetSymbolAddress((void**)&kvup,  g_kvup);
    cudaGetSymbolAddress((void**)&big2,  g_big2);
    cudaGetSymbolAddress((void**)&attn,  g_attn);
    cudaGetSymbolAddress((void**)&bt0,   g_bt0);
    cudaGetSymbolAddress((void**)&wuT,   g_wuT);
    cudaGetSymbolAddress((void**)&bt2,   g_bt2);
    cudaGetSymbolAddress((void**)&woT,   g_woT);
    cudaGetSymbolAddress((void**)&bias0, g_bias0);
    cudaGetSymbolAddress((void**)&bias2, g_bias2);

    cudaFuncSetAttribute(gemm_cp, cudaFuncAttributeMaxDynamicSharedMemorySize,
                         GEMM_SMEM);
    cudaFuncSetAttribute(flash_mma, cudaFuncAttributeMaxDynamicSharedMemorySize,
                         FL_SMEM);

    // L0: pre-round x
    round_tf32_kernel<<<(NTOK*DMODEL/4 + 255)/256, 256>>>(x, xt, NTOK*DMODEL/4);
    // L1: fused transpose [Wd|Wqd|Wkr] -> bt0   (grid 72 x 64)
    transpose_multi<<<dim3(N0/32, DMODEL/32), dim3(32, 8)>>>(
        Wd, DC, Wqd, DCOMP, Wkr, NH*DRP, bt0, DMODEL);
    // L2: bias0 = [bd|bqd|bkr]
    concat_bias3<<<(N0 + 255)/256, 256>>>(bias0, bd, DC, bqd, DCOMP, bkr, NH*DRP);
    // L3: G1 mega-GEMM x @ [Wd|Wqd|Wkr]  <-- PROFILED (576 CTAs)
    launch_gemm(xt, DMODEL, bt0, bias0, big0, N0, N0, DMODEL, 1);
    // L4: transpose Wu
    transpose_multi<<<dim3(DMODEL/32, DC/32), dim3(32, 8)>>>(
        Wu, DMODEL, Wu, 0, Wu, 0, wuT, DC);
    // L5: kv_up GEMM (A = kv_c slice of big0)
    launch_gemm(big0, N0, wuT, bu, kvup, DMODEL, DMODEL, DC, 1);
    // L6: fused transpose [Wqu|Wqr] -> bt2  (grid 96 x 24)
    transpose_multi<<<dim3(N2/32, DCOMP/32), dim3(32, 8)>>>(
        Wqu, DMODEL, Wqr, NH*DRP, Wqr, 0, bt2, DCOMP);
    // L7: bias2 = [bqu|bqr]
    concat_bias3<<<(N2 + 255)/256, 256>>>(bias2, bqu, DMODEL, bqr, NH*DRP,
                                          bqr, 0);
    // L8: fused (q_c | q_r) GEMM ; A = q_cmp slice of big0
    launch_gemm(big0 + QCMP_OFF, N0, bt2, bias2, big2, N2, N2, DCOMP, 1);

    {
        int n = NTOK * NH * 32;
        int blocks = (n + 255) / 256;
        rope_kernel<<<blocks, 256>>>(big2, N2, QR_OFF, n);    // L9  (q_r)
        rope_kernel<<<blocks, 256>>>(big0, N0, KR_OFF0, n);   // L10 (k_r)
    }

    // L11: transpose Wo
    transpose_multi<<<dim3(DMODEL/32, DMODEL/32), dim3(32, 8)>>>(
        Wo, DMODEL, Wo, 0, Wo, 0, woT, DMODEL);

    // L12: attention
    {
        dim3 grid(SS / 128, NH, BB);
        flash_mma<<<grid, 256, FL_SMEM>>>(big2, kvup, big0, attn);
    }

    // L13: output projection (full fp32 output)
    launch_gemm(attn, DMODEL, woT, bo, out, DMODEL, DMODEL, DMODEL, 0);
}

// round 9
// speedup vs baseline: 3.4499x; 1.1231x over previous
#include <cuda_runtime.h>
#include <math.h>
#include <stdint.h>

#define BB 2
#define SS 2048
#define NH 16
#define DHD 128
#define DRP 64
#define DMODEL 2048
#define DC 512
#define DCOMP 768
#define NTOK (BB*SS)

#define N0 (DC + DCOMP + NH*DRP)     // 2304  (kv_c | q_cmp | k_r)
#define QCMP_OFF DC                  // 512
#define KR_OFF0 (DC + DCOMP)         // 1280
#define N2 (DMODEL + NH*DRP)         // 3072  (q_c | q_r)
#define QR_OFF DMODEL                // 2048

// ---------------- scratch (static device globals; no allocation) ----------------
__device__ float g_xt  [NTOK*DMODEL];
__device__ float g_big0[NTOK*N0];      // [4096][2304] : kv_c | q_cmp | k_r
__device__ float g_kvup[NTOK*DMODEL];
__device__ float g_big2[NTOK*N2];      // [4096][3072] : q_c | q_r
__device__ float g_attn[NTOK*DMODEL];
__device__ float g_bt0 [N0*DMODEL];    // [Wd|Wqd|Wkr]^T
__device__ float g_wuT [DMODEL*DC];
__device__ float g_bt2 [N2*DCOMP];     // [Wqu|Wqr]^T
__device__ float g_woT [DMODEL*DMODEL];
__device__ float g_bias0[N0];
__device__ float g_bias2[N2];

__device__ __forceinline__ uint32_t f2tf32(float x) {
    uint32_t r;
    asm("cvt.rna.tf32.f32 %0, %1;" : "=r"(r) : "f"(x));
    return r;
}
__device__ __forceinline__ float roundtf(float x) {
    return __uint_as_float(f2tf32(x));
}
__device__ __forceinline__ uint32_t smem_u32(const void* p) {
    uint32_t a;
    asm("{ .reg .u64 t; cvta.to.shared.u64 t, %1; cvt.u32.u64 %0, t; }"
        : "=r"(a) : "l"(p));
    return a;
}

#define MMA_TF32(d0,d1,d2,d3, a0,a1,a2,a3, b0,b1) \
    asm volatile( \
        "mma.sync.aligned.m16n8k8.row.col.f32.tf32.tf32.f32 " \
        "{%0,%1,%2,%3}, {%4,%5,%6,%7}, {%8,%9}, {%0,%1,%2,%3};" \
        : "+f"(d0), "+f"(d1), "+f"(d2), "+f"(d3) \
        : "r"(a0), "r"(a1), "r"(a2), "r"(a3), "r"(b0), "r"(b1))

#define CP_ASYNC16(dst, src) \
    asm volatile("cp.async.cg.shared.global [%0], [%1], 16;" \
                 :: "r"(dst), "l"(src))
#define CP_COMMIT() asm volatile("cp.async.commit_group;" ::: "memory")
#define CP_WAIT1()  asm volatile("cp.async.wait_group 1;" ::: "memory")
#define CP_WAIT0()  asm volatile("cp.async.wait_group 0;" ::: "memory")

// ================= helpers =================
__global__ void round_tf32_kernel(const float* __restrict__ in,
                                  float* __restrict__ out, int n4)
{
    int i = blockIdx.x * blockDim.x + threadIdx.x;
    if (i >= n4) return;
    float4 v = ((const float4*)in)[i];
    v.x = roundtf(v.x); v.y = roundtf(v.y);
    v.z = roundtf(v.z); v.w = roundtf(v.w);
    ((float4*)out)[i] = v;
}

__global__ void concat_bias3(float* __restrict__ dst,
                             const float* __restrict__ a, int na,
                             const float* __restrict__ b, int nb,
                             const float* __restrict__ c, int nc)
{
    int i = blockIdx.x * blockDim.x + threadIdx.x;
    if (i < na) dst[i] = a[i];
    else if (i < na + nb) dst[i] = b[i - na];
    else if (i < na + nb + nc) dst[i] = c[i - na - nb];
}

// transpose up to 3 concatenated weight matrices (shared K) into out[n][k], tf32-rounded
__global__ void transpose_multi(
    const float* __restrict__ in0, int nsz0,
    const float* __restrict__ in1, int nsz1,
    const float* __restrict__ in2, int nsz2,
    float* __restrict__ out, int K)
{
    __shared__ float t[32][33];
    int gn = blockIdx.x * 32;
    int k0 = blockIdx.y * 32;
    const float* src; int N; int col0;
    if (gn < nsz0)              { src = in0; N = nsz0; col0 = gn; }
    else if (gn < nsz0 + nsz1)  { src = in1; N = nsz1; col0 = gn - nsz0; }
    else                        { src = in2; N = nsz2; col0 = gn - nsz0 - nsz1; }
    int tx = threadIdx.x, ty = threadIdx.y;  // (32, 8)
    #pragma unroll
    for (int i = 0; i < 4; ++i)
        t[ty + 8*i][tx] = src[(size_t)(k0 + ty + 8*i) * N + col0 + tx];
    __syncthreads();
    #pragma unroll
    for (int i = 0; i < 4; ++i)
        out[(size_t)(gn + ty + 8*i) * K + k0 + tx] = roundtf(t[tx][ty + 8*i]);
}

// ================= cp.async 3-stage tf32 GEMM, 2 CTAs/SM, BK=32 ==============
#define GBK 32
#define GSTG 3
#define GLDW 36
#define GSTG_WORDS (256 * GLDW)
#define GEMM_SMEM (GSTG * GSTG_WORDS * 4)    // 110,592 B; x2 CTA = 221,184

__global__ __launch_bounds__(256, 2) void gemm_cp(
    const float* __restrict__ A, int lda,
    const float* __restrict__ Bt,
    const float* __restrict__ bias,
    float* __restrict__ C, int ldc,
    int N, int K, int round_out)
{
    extern __shared__ uint32_t gsm[];
    const int tid  = threadIdx.x;
    const int lane = tid & 31;
    const int wid  = tid >> 5;
    const int wm = wid >> 2, wn = wid & 3;
    const int gr = lane >> 2, gc = lane & 3;
    const int wr = wm * 64,  wc = wn * 32;

    const int row0 = blockIdx.y * 128;
    const int col0 = blockIdx.x * 128;
    const float* Ag = A  + (size_t)row0 * lda;
    const float* Bg = Bt + (size_t)col0 * K;

    const int crow = tid >> 3;
    const int ccol = (tid & 7) * 4;
    const uint32_t smbase = smem_u32(gsm);

    const int niter = K / GBK;

    auto issue_stage = [&](int it) {
        const int s = it % GSTG;
        const int ko = it * GBK;
        uint32_t as = smbase + (uint32_t)(s * GSTG_WORDS) * 4u;
        uint32_t bs = as + (uint32_t)(128 * GLDW) * 4u;
        #pragma unroll
        for (int c = 0; c < 4; ++c) {
            int r = crow + 32 * c;
            CP_ASYNC16(as + (uint32_t)(r * GLDW + ccol) * 4u,
                       Ag + (size_t)r * lda + ko + ccol);
            CP_ASYNC16(bs + (uint32_t)(r * GLDW + ccol) * 4u,
                       Bg + (size_t)r * K + ko + ccol);
        }
    };

    float acc[4][4][4];
    #pragma unroll
    for (int i = 0; i < 4; ++i)
        #pragma unroll
        for (int j = 0; j < 4; ++j)
            #pragma unroll
            for (int c = 0; c < 4; ++c) acc[i][j][c] = 0.f;

    issue_stage(0); CP_COMMIT();
    issue_stage(1); CP_COMMIT();

    for (int it = 0; it < niter; ++it) {
        CP_WAIT1();
        __syncthreads();

        if (it + 2 < niter) issue_stage(it + 2);
        CP_COMMIT();

        const uint32_t* As = gsm + (it % GSTG) * GSTG_WORDS;
        const uint32_t* Bs = As + 128 * GLDW;

        #pragma unroll
        for (int ks = 0; ks < 4; ++ks) {
            const int k0 = ks * 8;
            uint32_t a[4][4], b[4][2];
            #pragma unroll
            for (int i = 0; i < 4; ++i) {
                const uint32_t* base = As + (wr + 16*i + gr) * GLDW + k0 + gc;
                a[i][0] = base[0];
                a[i][2] = base[4];
                a[i][1] = base[8 * GLDW];
                a[i][3] = base[8 * GLDW + 4];
            }
            #pragma unroll
            for (int j = 0; j < 4; ++j) {
                const uint32_t* base = Bs + (wc + 8*j + gr) * GLDW + k0 + gc;
                b[j][0] = base[0];
                b[j][1] = base[4];
            }
            #pragma unroll
            for (int i = 0; i < 4; ++i)
                #pragma unroll
                for (int j = 0; j < 4; ++j)
                    MMA_TF32(acc[i][j][0], acc[i][j][1], acc[i][j][2], acc[i][j][3],
                             a[i][0], a[i][1], a[i][2], a[i][3], b[j][0], b[j][1]);
        }
        __syncthreads();
    }

    #pragma unroll
    for (int j = 0; j < 4; ++j) {
        int c = col0 + wc + 8*j + 2*gc;
        float bv0 = bias[c], bv1 = bias[c + 1];
        #pragma unroll
        for (int i = 0; i < 4; ++i) {
            int r = row0 + wr + 16*i + gr;
            float f0 = acc[i][j][0] + bv0, f1 = acc[i][j][1] + bv1;
            float f2 = acc[i][j][2] + bv0, f3 = acc[i][j][3] + bv1;
            if (round_out) {
                f0 = roundtf(f0); f1 = roundtf(f1);
                f2 = roundtf(f2); f3 = roundtf(f3);
            }
            *(float2*)(C + (size_t)r * ldc + c)       = make_float2(f0, f1);
            *(float2*)(C + (size_t)(r + 8) * ldc + c) = make_float2(f2, f3);
        }
    }
}

// ================= RoPE (in place on a column slice), rounds to tf32 ==========
__global__ void rope_kernel(float* __restrict__ buf, int ld, int off, int n)
{
    int idx = blockIdx.x * blockDim.x + threadIdx.x;
    if (idx >= n) return;
    int i = idx & 31;
    int h = (idx >> 5) & (NH - 1);
    int t = idx >> 9;
    int pos = t & (SS - 1);

    float freq = exp2f(-13.287712379549449f * (float)i / 32.0f);
    float ang = (float)pos * freq;
    float sn, cs;
    sincosf(ang, &sn, &cs);

    float* p = buf + (size_t)t * ld + off + h * DRP + 2 * i;
    float x1 = p[0], x2 = p[1];
    p[0] = roundtf(x1 * cs - x2 * sn);
    p[1] = roundtf(x1 * sn + x2 * cs);
}

// ================= flash attention v3: cp.async K pipeline + P in registers ===
// smem: Qs [128][196] + K double buffer 2x[64][196]  = 200,704 B, 1 CTA/SM.
#define ALDQ 196
#define KBUF_WORDS (64 * ALDQ)                 // 12544
#define FL_SMEM ((128 * ALDQ + 2 * KBUF_WORDS) * 4)   // 200,704 B

__global__ __launch_bounds__(256, 1) void flash_mma(
    const float* __restrict__ qcr,    // big2: q_c cols [0,2048), q_r at QR_OFF; ld N2
    const float* __restrict__ kvup,   // [4096][2048]
    const float* __restrict__ krb,    // big0: k_r at KR_OFF0; ld N0
    float* __restrict__ out)
{
    extern __shared__ uint32_t sm[];
    uint32_t* Qs = sm;                        // [128][196]
    uint32_t* Kbuf = sm + 128 * ALDQ;         // 2 x [64][196]
    const uint32_t kbase = smem_u32(Kbuf);

    const int tid  = threadIdx.x;
    const int wid  = tid >> 5;
    const int lane = tid & 31;
    const int gr = lane >> 2;
    const int gc = lane & 3;
    const int wq = wid * 16;
    const bool odd = (gc & 1);

    const int q0 = blockIdx.x * 128;
    const int h  = blockIdx.y;
    const int b  = blockIdx.z;
    const size_t tok0 = (size_t)b * SS;

    // ---- issue K tile t into buffer t&1 via cp.async ----
    auto issue_k = [&](int t) {
        const uint32_t kb = kbase + (uint32_t)((t & 1) * KBUF_WORDS) * 4u;
        const int k0tok = t * 64;
        #pragma unroll
        for (int i = 0; i < 8; ++i) {            // kvup cols: 64 rows x 32 chunks
            int idx = tid + 256 * i;
            int r = idx >> 5, cb = idx & 31;
            CP_ASYNC16(kb + (uint32_t)(r * ALDQ + cb * 4) * 4u,
                       kvup + (tok0 + k0tok + r) * (size_t)DMODEL + h * DHD + cb * 4);
        }
        #pragma unroll
        for (int i = 0; i < 4; ++i) {            // k_r cols: 64 rows x 16 chunks
            int idx = tid + 256 * i;
            int r = idx >> 4, cb = idx & 15;
            CP_ASYNC16(kb + (uint32_t)(r * ALDQ + 128 + cb * 4) * 4u,
                       krb + (tok0 + k0tok + r) * (size_t)N0 + KR_OFF0 + h * DRP + cb * 4);
        }
    };

    // prefetch tile 0 under the Q staging
    issue_k(0); CP_COMMIT();

    // ---- stage Q tile ----
    for (int idx = tid; idx < 128 * 32; idx += 256) {
        int r = idx >> 5, c4 = (idx & 31) * 4;
        *(uint4*)(Qs + r * ALDQ + c4) =
            *(const uint4*)(qcr + (tok0 + q0 + r) * N2 + h * DHD + c4);
    }
    for (int idx = tid; idx < 128 * 16; idx += 256) {
        int r = idx >> 4, c4 = (idx & 15) * 4;
        *(uint4*)(Qs + r * ALDQ + 128 + c4) =
            *(const uint4*)(qcr + (tok0 + q0 + r) * N2 + QR_OFF + h * DRP + c4);
    }

    float m0 = -INFINITY, m1 = -INFINITY, l0 = 0.f, l1 = 0.f;
    float o[16][4];
    #pragma unroll
    for (int j = 0; j < 16; ++j)
        #pragma unroll
        for (int c = 0; c < 4; ++c) o[j][c] = 0.f;

    const float scale = 0.08838834764831845f;  // 1/sqrt(128)
    const int srcA = gc >> 1;                  // width-4 shuffle sources
    const int srcB = 2 + (gc >> 1);

    for (int kt = 0; kt < SS / 64; ++kt) {
        if (kt + 1 < SS / 64) issue_k(kt + 1);
        CP_COMMIT();
        if (kt + 1 < SS / 64) { CP_WAIT1(); } else { CP_WAIT0(); }
        __syncthreads();                        // tile kt visible (also Q on kt==0)

        const uint32_t* Kb = Kbuf + (kt & 1) * KBUF_WORDS;

        // ---- S = Q @ K^T ----
        float s[8][4];
        #pragma unroll
        for (int j = 0; j < 8; ++j)
            #pragma unroll
            for (int c = 0; c < 4; ++c) s[j][c] = 0.f;

        #pragma unroll 4
        for (int ks = 0; ks < 24; ++ks) {
            const int k0 = ks * 8;
            const uint32_t* abase = Qs + (wq + gr) * ALDQ + k0 + gc;
            uint32_t a0 = abase[0];
            uint32_t a2 = abase[4];
            uint32_t a1 = abase[8 * ALDQ];
            uint32_t a3 = abase[8 * ALDQ + 4];
            #pragma unroll
            for (int j = 0; j < 8; ++j) {
                const uint32_t* bbase = Kb + (8*j + gr) * ALDQ + k0 + gc;
                uint32_t b0 = bbase[0];
                uint32_t b1 = bbase[4];
                MMA_TF32(s[j][0], s[j][1], s[j][2], s[j][3], a0, a1, a2, a3, b0, b1);
            }
        }

        // ---- online softmax; P stays in s[][] ----
        float mx0 = -INFINITY, mx1 = -INFINITY;
        #pragma unroll
        for (int j = 0; j < 8; ++j) {
            s[j][0] *= scale; s[j][1] *= scale; s[j][2] *= scale; s[j][3] *= scale;
            mx0 = fmaxf(mx0, fmaxf(s[j][0], s[j][1]));
            mx1 = fmaxf(mx1, fmaxf(s[j][2], s[j][3]));
        }
        #pragma unroll
        for (int off = 1; off <= 2; off <<= 1) {
            mx0 = fmaxf(mx0, __shfl_xor_sync(0xffffffffu, mx0, off));
            mx1 = fmaxf(mx1, __shfl_xor_sync(0xffffffffu, mx1, off));
        }
        float m0n = fmaxf(m0, mx0);
        float m1n = fmaxf(m1, mx1);
        float al0 = __expf(m0 - m0n);
        float al1 = __expf(m1 - m1n);
        float rs0 = 0.f, rs1 = 0.f;
        #pragma unroll
        for (int j = 0; j < 8; ++j) {
            s[j][0] = __expf(s[j][0] - m0n);
            s[j][1] = __expf(s[j][1] - m0n);
            s[j][2] = __expf(s[j][2] - m1n);
            s[j][3] = __expf(s[j][3] - m1n);
            rs0 += s[j][0] + s[j][1];
            rs1 += s[j][2] + s[j][3];
        }
        #pragma unroll
        for (int off = 1; off <= 2; off <<= 1) {
            rs0 += __shfl_xor_sync(0xffffffffu, rs0, off);
            rs1 += __shfl_xor_sync(0xffffffffu, rs1, off);
        }
        l0 = l0 * al0 + rs0;
        l1 = l1 * al1 + rs1;
        m0 = m0n; m1 = m1n;
        #pragma unroll
        for (int j = 0; j < 16; ++j) {
            o[j][0] *= al0; o[j][1] *= al0;
            o[j][2] *= al1; o[j][3] *= al1;
        }

        // ---- O += P @ V : A-fragments from registers via width-4 shuffles ----
        #pragma unroll 2
        for (int ks = 0; ks < 8; ++ks) {
            const int k0 = ks * 8;
            float v0 = __shfl_sync(0xffffffffu, s[ks][0], srcA, 4);
            float v1 = __shfl_sync(0xffffffffu, s[ks][1], srcA, 4);
            float v2 = __shfl_sync(0xffffffffu, s[ks][2], srcA, 4);
            float v3 = __shfl_sync(0xffffffffu, s[ks][3], srcA, 4);
            float w0 = __shfl_sync(0xffffffffu, s[ks][0], srcB, 4);
            float w1 = __shfl_sync(0xffffffffu, s[ks][1], srcB, 4);
            float w2 = __shfl_sync(0xffffffffu, s[ks][2], srcB, 4);
            float w3 = __shfl_sync(0xffffffffu, s[ks][3], srcB, 4);
            uint32_t a0 = f2tf32(odd ? v1 : v0);
            uint32_t a1 = f2tf32(odd ? v3 : v2);
            uint32_t a2 = f2tf32(odd ? w1 : w0);
            uint32_t a3 = f2tf32(odd ? w3 : w2);
            #pragma unroll
            for (int j = 0; j < 16; ++j) {
                uint32_t b0 = Kb[(k0 + gc) * ALDQ + 8*j + gr];
                uint32_t b1 = Kb[(k0 + gc + 4) * ALDQ + 8*j + gr];
                MMA_TF32(o[j][0], o[j][1], o[j][2], o[j][3], a0, a1, a2, a3, b0, b1);
            }
        }
        __syncthreads();   // all warps done with Kbuf[kt&1] before reissue
    }

    // ---- epilogue (write tf32-rounded attn for the Wo GEMM) ----
    float inv0 = 1.0f / l0;
    float inv1 = 1.0f / l1;
    size_t r0 = (tok0 + q0 + wq + gr) * DMODEL + h * DHD;
    size_t r1 = (tok0 + q0 + wq + gr + 8) * DMODEL + h * DHD;
    #pragma unroll
    for (int j = 0; j < 16; ++j) {
        int c = 8*j + 2*gc;
        *(float2*)(out + r0 + c) =
            make_float2(roundtf(o[j][0] * inv0), roundtf(o[j][1] * inv0));
        *(float2*)(out + r1 + c) =
            make_float2(roundtf(o[j][2] * inv1), roundtf(o[j][3] * inv1));
    }
}

// ================= host launch =================
static inline void launch_gemm(const float* A, int lda, const float* Bt,
                               const float* bias, float* C, int ldc,
                               int N, int K, int round_out)
{
    dim3 grid(N / 128, NTOK / 128);
    gemm_cp<<<grid, 256, GEMM_SMEM>>>(A, lda, Bt, bias, C, ldc, N, K, round_out);
}

extern "C" void kernel_launch(void* const* d_in, const int* in_sizes, int n_in,
                              void* d_out, int out_size)
{
    (void)in_sizes; (void)n_in; (void)out_size;
    const float* x   = (const float*)d_in[0];
    const float* Wd  = (const float*)d_in[1];
    const float* bd  = (const float*)d_in[2];
    const float* Wu  = (const float*)d_in[3];
    const float* bu  = (const float*)d_in[4];
    const float* Wqd = (const float*)d_in[5];
    const float* bqd = (const float*)d_in[6];
    const float* Wqu = (const float*)d_in[7];
    const float* bqu = (const float*)d_in[8];
    const float* Wqr = (const float*)d_in[9];
    const float* bqr = (const float*)d_in[10];
    const float* Wkr = (const float*)d_in[11];
    const float* bkr = (const float*)d_in[12];
    const float* Wo  = (const float*)d_in[13];
    const float* bo  = (const float*)d_in[14];
    float* out = (float*)d_out;

    float *xt, *big0, *kvup, *big2, *attn;
    float *bt0, *wuT, *bt2, *woT, *bias0, *bias2;
    cudaGetSymbolAddress((void**)&xt,    g_xt);
    cudaGetSymbolAddress((void**)&big0,  g_big0);
    cudaGetSymbolAddress((void**)&kvup,  g_kvup);
    cudaGetSymbolAddress((void**)&big2,  g_big2);
    cudaGetSymbolAddress((void**)&attn,  g_attn);
    cudaGetSymbolAddress((void**)&bt0,   g_bt0);
    cudaGetSymbolAddress((void**)&wuT,   g_wuT);
    cudaGetSymbolAddress((void**)&bt2,   g_bt2);
    cudaGetSymbolAddress((void**)&woT,   g_woT);
    cudaGetSymbolAddress((void**)&bias0, g_bias0);
    cudaGetSymbolAddress((void**)&bias2, g_bias2);

    cudaFuncSetAttribute(gemm_cp, cudaFuncAttributeMaxDynamicSharedMemorySize,
                         GEMM_SMEM);
    cudaFuncSetAttribute(flash_mma, cudaFuncAttributeMaxDynamicSharedMemorySize,
                         FL_SMEM);

    // L0: pre-round x
    round_tf32_kernel<<<(NTOK*DMODEL/4 + 255)/256, 256>>>(x, xt, NTOK*DMODEL/4);
    // L1: fused transpose [Wd|Wqd|Wkr] -> bt0
    transpose_multi<<<dim3(N0/32, DMODEL/32), dim3(32, 8)>>>(
        Wd, DC, Wqd, DCOMP, Wkr, NH*DRP, bt0, DMODEL);
    // L2: bias0
    concat_bias3<<<(N0 + 255)/256, 256>>>(bias0, bd, DC, bqd, DCOMP, bkr, NH*DRP);
    // L3: G1 mega-GEMM  <-- PROFILED
    launch_gemm(xt, DMODEL, bt0, bias0, big0, N0, N0, DMODEL, 1);
    // L4: transpose Wu
    transpose_multi<<<dim3(DMODEL/32, DC/32), dim3(32, 8)>>>(
        Wu, DMODEL, Wu, 0, Wu, 0, wuT, DC);
    // L5: kv_up GEMM
    launch_gemm(big0, N0, wuT, bu, kvup, DMODEL, DMODEL, DC, 1);
    // L6: fused transpose [Wqu|Wqr] -> bt2
    transpose_multi<<<dim3(N2/32, DCOMP/32), dim3(32, 8)>>>(
        Wqu, DMODEL, Wqr, NH*DRP, Wqr, 0, bt2, DCOMP);
    // L7: bias2
    concat_bias3<<<(N2 + 255)/256, 256>>>(bias2, bqu, DMODEL, bqr, NH*DRP,
                                          bqr, 0);
    // L8: fused (q_c | q_r) GEMM
    launch_gemm(big0 + QCMP_OFF, N0, bt2, bias2, big2, N2, N2, DCOMP, 1);

    {
        int n = NTOK * NH * 32;
        int blocks = (n + 255) / 256;
        rope_kernel<<<blocks, 256>>>(big2, N2, QR_OFF, n);    // q_r
        rope_kernel<<<blocks, 256>>>(big0, N0, KR_OFF0, n);   // k_r
    }

    // transpose Wo
    transpose_multi<<<dim3(DMODEL/32, DMODEL/32), dim3(32, 8)>>>(
        Wo, DMODEL, Wo, 0, Wo, 0, woT, DMODEL);

    // attention
    {
        dim3 grid(SS / 128, NH, BB);
        flash_mma<<<grid, 256, FL_SMEM>>>(big2, kvup, big0, attn);
    }

    // output projection (full fp32 output)
    launch_gemm(attn, DMODEL, woT, bo, out, DMODEL, DMODEL, DMODEL, 0);
}

// round 10
// speedup vs baseline: 3.6518x; 1.0585x over previous
#include <cuda_runtime.h>
#include <math.h>
#include <stdint.h>

#define BB 2
#define SS 2048
#define NH 16
#define DHD 128
#define DRP 64
#define DMODEL 2048
#define DC 512
#define DCOMP 768
#define NTOK (BB*SS)

#define N0 (DC + DCOMP + NH*DRP)     // 2304  (kv_c | q_cmp | k_r)
#define QCMP_OFF DC                  // 512
#define KR_OFF0 (DC + DCOMP)         // 1280
#define N2 (DMODEL + NH*DRP)         // 3072  (q_c | q_r)
#define QR_OFF DMODEL                // 2048

// ---------------- scratch (static device globals; no allocation) ----------------
__device__ float g_xt  [NTOK*DMODEL];
__device__ float g_big0[NTOK*N0];      // [4096][2304] : kv_c | q_cmp | k_r
__device__ float g_kvup[NTOK*DMODEL];
__device__ float g_big2[NTOK*N2];      // [4096][3072] : q_c | q_r
__device__ float g_attn[NTOK*DMODEL];
__device__ float g_bt0 [N0*DMODEL];    // [Wd|Wqd|Wkr]^T
__device__ float g_wuT [DMODEL*DC];
__device__ float g_bt2 [N2*DCOMP];     // [Wqu|Wqr]^T
__device__ float g_woT [DMODEL*DMODEL];
__device__ float g_bias0[N0];
__device__ float g_bias2[N2];

__device__ __forceinline__ uint32_t f2tf32(float x) {
    uint32_t r;
    asm("cvt.rna.tf32.f32 %0, %1;" : "=r"(r) : "f"(x));
    return r;
}
__device__ __forceinline__ float roundtf(float x) {
    return __uint_as_float(f2tf32(x));
}
__device__ __forceinline__ uint32_t smem_u32(const void* p) {
    uint32_t a;
    asm("{ .reg .u64 t; cvta.to.shared.u64 t, %1; cvt.u32.u64 %0, t; }"
        : "=r"(a) : "l"(p));
    return a;
}

#define MMA_TF32(d0,d1,d2,d3, a0,a1,a2,a3, b0,b1) \
    asm volatile( \
        "mma.sync.aligned.m16n8k8.row.col.f32.tf32.tf32.f32 " \
        "{%0,%1,%2,%3}, {%4,%5,%6,%7}, {%8,%9}, {%0,%1,%2,%3};" \
        : "+f"(d0), "+f"(d1), "+f"(d2), "+f"(d3) \
        : "r"(a0), "r"(a1), "r"(a2), "r"(a3), "r"(b0), "r"(b1))

#define CP_ASYNC16(dst, src) \
    asm volatile("cp.async.cg.shared.global [%0], [%1], 16;" \
                 :: "r"(dst), "l"(src))
#define CP_COMMIT() asm volatile("cp.async.commit_group;" ::: "memory")
#define CP_WAIT1()  asm volatile("cp.async.wait_group 1;" ::: "memory")
#define CP_WAIT0()  asm volatile("cp.async.wait_group 0;" ::: "memory")

// ================= helpers =================
__global__ void round_tf32_kernel(const float* __restrict__ in,
                                  float* __restrict__ out, int n4)
{
    int i = blockIdx.x * blockDim.x + threadIdx.x;
    if (i >= n4) return;
    float4 v = ((const float4*)in)[i];
    v.x = roundtf(v.x); v.y = roundtf(v.y);
    v.z = roundtf(v.z); v.w = roundtf(v.w);
    ((float4*)out)[i] = v;
}

__global__ void concat_bias3(float* __restrict__ dst,
                             const float* __restrict__ a, int na,
                             const float* __restrict__ b, int nb,
                             const float* __restrict__ c, int nc)
{
    int i = blockIdx.x * blockDim.x + threadIdx.x;
    if (i < na) dst[i] = a[i];
    else if (i < na + nb) dst[i] = b[i - na];
    else if (i < na + nb + nc) dst[i] = c[i - na - nb];
}

// transpose up to 3 concatenated weight matrices (shared K) into out[n][k], tf32-rounded
__global__ void transpose_multi(
    const float* __restrict__ in0, int nsz0,
    const float* __restrict__ in1, int nsz1,
    const float* __restrict__ in2, int nsz2,
    float* __restrict__ out, int K)
{
    __shared__ float t[32][33];
    int gn = blockIdx.x * 32;
    int k0 = blockIdx.y * 32;
    const float* src; int N; int col0;
    if (gn < nsz0)              { src = in0; N = nsz0; col0 = gn; }
    else if (gn < nsz0 + nsz1)  { src = in1; N = nsz1; col0 = gn - nsz0; }
    else                        { src = in2; N = nsz2; col0 = gn - nsz0 - nsz1; }
    int tx = threadIdx.x, ty = threadIdx.y;  // (32, 8)
    #pragma unroll
    for (int i = 0; i < 4; ++i)
        t[ty + 8*i][tx] = src[(size_t)(k0 + ty + 8*i) * N + col0 + tx];
    __syncthreads();
    #pragma unroll
    for (int i = 0; i < 4; ++i)
        out[(size_t)(gn + ty + 8*i) * K + k0 + tx] = roundtf(t[tx][ty + 8*i]);
}

// ================= cp.async 3-stage tf32 GEMM body, 2 CTAs/SM, BK=32 =========
#define GBK 32
#define GSTG 3
#define GLDW 36
#define GSTG_WORDS (256 * GLDW)
#define GEMM_SMEM (GSTG * GSTG_WORDS * 4)    // 110,592 B; x2 CTA = 221,184

__device__ __forceinline__ void gemm_body(
    const float* __restrict__ A, int lda,
    const float* __restrict__ Bt,
    const float* __restrict__ bias,
    float* __restrict__ C, int ldc,
    int K, int row0, int col0,
    uint32_t* gsm, int round_out)
{
    const int tid  = threadIdx.x;
    const int lane = tid & 31;
    const int wid  = tid >> 5;
    const int wm = wid >> 2, wn = wid & 3;
    const int gr = lane >> 2, gc = lane & 3;
    const int wr = wm * 64,  wc = wn * 32;

    const float* Ag = A  + (size_t)row0 * lda;
    const float* Bg = Bt + (size_t)col0 * K;

    const int crow = tid >> 3;
    const int ccol = (tid & 7) * 4;
    const uint32_t smbase = smem_u32(gsm);

    const int niter = K / GBK;

    auto issue_stage = [&](int it) {
        const int s = it % GSTG;
        const int ko = it * GBK;
        uint32_t as = smbase + (uint32_t)(s * GSTG_WORDS) * 4u;
        uint32_t bs = as + (uint32_t)(128 * GLDW) * 4u;
        #pragma unroll
        for (int c = 0; c < 4; ++c) {
            int r = crow + 32 * c;
            CP_ASYNC16(as + (uint32_t)(r * GLDW + ccol) * 4u,
                       Ag + (size_t)r * lda + ko + ccol);
            CP_ASYNC16(bs + (uint32_t)(r * GLDW + ccol) * 4u,
                       Bg + (size_t)r * K + ko + ccol);
        }
    };

    float acc[4][4][4];
    #pragma unroll
    for (int i = 0; i < 4; ++i)
        #pragma unroll
        for (int j = 0; j < 4; ++j)
            #pragma unroll
            for (int c = 0; c < 4; ++c) acc[i][j][c] = 0.f;

    issue_stage(0); CP_COMMIT();
    issue_stage(1); CP_COMMIT();

    for (int it = 0; it < niter; ++it) {
        CP_WAIT1();
        __syncthreads();   // all warps done reading stage it-1 (slot (it+2)%3)

        if (it + 2 < niter) issue_stage(it + 2);
        CP_COMMIT();

        const uint32_t* As = gsm + (it % GSTG) * GSTG_WORDS;
        const uint32_t* Bs = As + 128 * GLDW;

        #pragma unroll
        for (int ks = 0; ks < 4; ++ks) {
            const int k0 = ks * 8;
            uint32_t a[4][4], b[4][2];
            #pragma unroll
            for (int i = 0; i < 4; ++i) {
                const uint32_t* base = As + (wr + 16*i + gr) * GLDW + k0 + gc;
                a[i][0] = base[0];
                a[i][2] = base[4];
                a[i][1] = base[8 * GLDW];
                a[i][3] = base[8 * GLDW + 4];
            }
            #pragma unroll
            for (int j = 0; j < 4; ++j) {
                const uint32_t* base = Bs + (wc + 8*j + gr) * GLDW + k0 + gc;
                b[j][0] = base[0];
                b[j][1] = base[4];
            }
            #pragma unroll
            for (int i = 0; i < 4; ++i)
                #pragma unroll
                for (int j = 0; j < 4; ++j)
                    MMA_TF32(acc[i][j][0], acc[i][j][1], acc[i][j][2], acc[i][j][3],
                             a[i][0], a[i][1], a[i][2], a[i][3], b[j][0], b[j][1]);
        }
        // no trailing barrier: top-of-loop sync provides the ordering
    }

    #pragma unroll
    for (int j = 0; j < 4; ++j) {
        int c = col0 + wc + 8*j + 2*gc;
        float bv0 = bias[c], bv1 = bias[c + 1];
        #pragma unroll
        for (int i = 0; i < 4; ++i) {
            int r = row0 + wr + 16*i + gr;
            float f0 = acc[i][j][0] + bv0, f1 = acc[i][j][1] + bv1;
            float f2 = acc[i][j][2] + bv0, f3 = acc[i][j][3] + bv1;
            if (round_out) {
                f0 = roundtf(f0); f1 = roundtf(f1);
                f2 = roundtf(f2); f3 = roundtf(f3);
            }
            *(float2*)(C + (size_t)r * ldc + c)       = make_float2(f0, f1);
            *(float2*)(C + (size_t)(r + 8) * ldc + c) = make_float2(f2, f3);
        }
    }
}

__global__ __launch_bounds__(256, 2) void gemm_cp(
    const float* __restrict__ A, int lda,
    const float* __restrict__ Bt,
    const float* __restrict__ bias,
    float* __restrict__ C, int ldc,
    int K, int round_out)
{
    extern __shared__ uint32_t gsm[];
    gemm_body(A, lda, Bt, bias, C, ldc, K,
              blockIdx.y * 128, blockIdx.x * 128, gsm, round_out);
}

// fused launch: cols [0,split) -> GEMM0 params, cols [split,..) -> GEMM1 params
__global__ __launch_bounds__(256, 2) void gemm_dual(
    const float* __restrict__ A0, int lda0, const float* __restrict__ Bt0,
    const float* __restrict__ bias0, float* __restrict__ C0, int ldc0, int K0,
    const float* __restrict__ A1, int lda1, const float* __restrict__ Bt1,
    const float* __restrict__ bias1, float* __restrict__ C1, int ldc1, int K1,
    int split)
{
    extern __shared__ uint32_t gsm[];
    if ((int)blockIdx.x < split)
        gemm_body(A0, lda0, Bt0, bias0, C0, ldc0, K0,
                  blockIdx.y * 128, blockIdx.x * 128, gsm, 1);
    else
        gemm_body(A1, lda1, Bt1, bias1, C1, ldc1, K1,
                  blockIdx.y * 128, (blockIdx.x - split) * 128, gsm, 1);
}

// ================= fused RoPE for q_r (big2) and k_r (big0) =================
__global__ void rope_kernel2(float* __restrict__ b2, float* __restrict__ b0, int n)
{
    int idx = blockIdx.x * blockDim.x + threadIdx.x;
    int which = (idx >= n);
    int id = which ? idx - n : idx;
    if (id >= n) return;
    int i = id & 31;
    int h = (id >> 5) & (NH - 1);
    int t = id >> 9;
    int pos = t & (SS - 1);

    float freq = exp2f(-13.287712379549449f * (float)i / 32.0f);
    float ang = (float)pos * freq;
    float sn, cs;
    sincosf(ang, &sn, &cs);

    float* p = which
        ? b0 + (size_t)t * N0 + KR_OFF0 + h * DRP + 2 * i
        : b2 + (size_t)t * N2 + QR_OFF  + h * DRP + 2 * i;
    float x1 = p[0], x2 = p[1];
    p[0] = roundtf(x1 * cs - x2 * sn);
    p[1] = roundtf(x1 * sn + x2 * cs);
}

// ================= flash attention v4 ==========================
// ALDQ=200 (conflict-free PV loads); Q fragments held in registers.
#define ALDQ 200
#define KBUF_WORDS (64 * ALDQ)                        // 12800
#define FL_SMEM ((128 * ALDQ + 2 * KBUF_WORDS) * 4)   // 204,800 B

__global__ __launch_bounds__(256, 1) void flash_mma(
    const float* __restrict__ qcr,    // big2: q_c cols [0,2048), q_r at QR_OFF; ld N2
    const float* __restrict__ kvup,   // [4096][2048]
    const float* __restrict__ krb,    // big0: k_r at KR_OFF0; ld N0
    float* __restrict__ out)
{
    extern __shared__ uint32_t sm[];
    uint32_t* Qs = sm;                        // [128][200]
    uint32_t* Kbuf = sm + 128 * ALDQ;         // 2 x [64][200]
    const uint32_t kbase = smem_u32(Kbuf);

    const int tid  = threadIdx.x;
    const int wid  = tid >> 5;
    const int lane = tid & 31;
    const int gr = lane >> 2;
    const int gc = lane & 3;
    const int wq = wid * 16;
    const bool odd = (gc & 1);

    const int q0 = blockIdx.x * 128;
    const int h  = blockIdx.y;
    const int b  = blockIdx.z;
    const size_t tok0 = (size_t)b * SS;

    auto issue_k = [&](int t) {
        const uint32_t kb = kbase + (uint32_t)((t & 1) * KBUF_WORDS) * 4u;
        const int k0tok = t * 64;
        #pragma unroll
        for (int i = 0; i < 8; ++i) {            // kvup cols: 64 rows x 32 chunks
            int idx = tid + 256 * i;
            int r = idx >> 5, cb = idx & 31;
            CP_ASYNC16(kb + (uint32_t)(r * ALDQ + cb * 4) * 4u,
                       kvup + (tok0 + k0tok + r) * (size_t)DMODEL + h * DHD + cb * 4);
        }
        #pragma unroll
        for (int i = 0; i < 4; ++i) {            // k_r cols: 64 rows x 16 chunks
            int idx = tid + 256 * i;
            int r = idx >> 4, cb = idx & 15;
            CP_ASYNC16(kb + (uint32_t)(r * ALDQ + 128 + cb * 4) * 4u,
                       krb + (tok0 + k0tok + r) * (size_t)N0 + KR_OFF0 + h * DRP + cb * 4);
        }
    };

    issue_k(0); CP_COMMIT();

    // ---- stage Q tile ----
    for (int idx = tid; idx < 128 * 32; idx += 256) {
        int r = idx >> 5, c4 = (idx & 31) * 4;
        *(uint4*)(Qs + r * ALDQ + c4) =
            *(const uint4*)(qcr + (tok0 + q0 + r) * N2 + h * DHD + c4);
    }
    for (int idx = tid; idx < 128 * 16; idx += 256) {
        int r = idx >> 4, c4 = (idx & 15) * 4;
        *(uint4*)(Qs + r * ALDQ + 128 + c4) =
            *(const uint4*)(qcr + (tok0 + q0 + r) * N2 + QR_OFF + h * DRP + c4);
    }
    __syncthreads();

    // ---- hoist Q fragments into registers (loop-invariant across key tiles) ----
    uint32_t qf[24][4];
    #pragma unroll
    for (int ks = 0; ks < 24; ++ks) {
        const uint32_t* abase = Qs + (wq + gr) * ALDQ + ks * 8 + gc;
        qf[ks][0] = abase[0];
        qf[ks][2] = abase[4];
        qf[ks][1] = abase[8 * ALDQ];
        qf[ks][3] = abase[8 * ALDQ + 4];
    }

    float m0 = -INFINITY, m1 = -INFINITY, l0 = 0.f, l1 = 0.f;
    float o[16][4];
    #pragma unroll
    for (int j = 0; j < 16; ++j)
        #pragma unroll
        for (int c = 0; c < 4; ++c) o[j][c] = 0.f;

    const float scale = 0.08838834764831845f;  // 1/sqrt(128)
    const int srcA = gc >> 1;
    const int srcB = 2 + (gc >> 1);

    for (int kt = 0; kt < SS / 64; ++kt) {
        if (kt + 1 < SS / 64) issue_k(kt + 1);
        CP_COMMIT();
        if (kt + 1 < SS / 64) { CP_WAIT1(); } else { CP_WAIT0(); }
        __syncthreads();

        const uint32_t* Kb = Kbuf + (kt & 1) * KBUF_WORDS;

        // ---- S = Q @ K^T ----
        float s[8][4];
        #pragma unroll
        for (int j = 0; j < 8; ++j)
            #pragma unroll
            for (int c = 0; c < 4; ++c) s[j][c] = 0.f;

        #pragma unroll
        for (int ks = 0; ks < 24; ++ks) {
            const int k0 = ks * 8;
            #pragma unroll
            for (int j = 0; j < 8; ++j) {
                const uint32_t* bbase = Kb + (8*j + gr) * ALDQ + k0 + gc;
                uint32_t b0 = bbase[0];
                uint32_t b1 = bbase[4];
                MMA_TF32(s[j][0], s[j][1], s[j][2], s[j][3],
                         qf[ks][0], qf[ks][1], qf[ks][2], qf[ks][3], b0, b1);
            }
        }

        // ---- online softmax; P stays in s[][] ----
        float mx0 = -INFINITY, mx1 = -INFINITY;
        #pragma unroll
        for (int j = 0; j < 8; ++j) {
            s[j][0] *= scale; s[j][1] *= scale; s[j][2] *= scale; s[j][3] *= scale;
            mx0 = fmaxf(mx0, fmaxf(s[j][0], s[j][1]));
            mx1 = fmaxf(mx1, fmaxf(s[j][2], s[j][3]));
        }
        #pragma unroll
        for (int off = 1; off <= 2; off <<= 1) {
            mx0 = fmaxf(mx0, __shfl_xor_sync(0xffffffffu, mx0, off));
            mx1 = fmaxf(mx1, __shfl_xor_sync(0xffffffffu, mx1, off));
        }
        float m0n = fmaxf(m0, mx0);
        float m1n = fmaxf(m1, mx1);
        float al0 = __expf(m0 - m0n);
        float al1 = __expf(m1 - m1n);
        float rs0 = 0.f, rs1 = 0.f;
        #pragma unroll
        for (int j = 0; j < 8; ++j) {
            s[j][0] = __expf(s[j][0] - m0n);
            s[j][1] = __expf(s[j][1] - m0n);
            s[j][2] = __expf(s[j][2] - m1n);
            s[j][3] = __expf(s[j][3] - m1n);
            rs0 += s[j][0] + s[j][1];
            rs1 += s[j][2] + s[j][3];
        }
        #pragma unroll
        for (int off = 1; off <= 2; off <<= 1) {
            rs0 += __shfl_xor_sync(0xffffffffu, rs0, off);
            rs1 += __shfl_xor_sync(0xffffffffu, rs1, off);
        }
        l0 = l0 * al0 + rs0;
        l1 = l1 * al1 + rs1;
        m0 = m0n; m1 = m1n;
        #pragma unroll
        for (int j = 0; j < 16; ++j) {
            o[j][0] *= al0; o[j][1] *= al0;
            o[j][2] *= al1; o[j][3] *= al1;
        }

        // ---- O += P @ V : A-fragments from registers via width-4 shuffles ----
        #pragma unroll 2
        for (int ks = 0; ks < 8; ++ks) {
            const int k0 = ks * 8;
            float v0 = __shfl_sync(0xffffffffu, s[ks][0], srcA, 4);
            float v1 = __shfl_sync(0xffffffffu, s[ks][1], srcA, 4);
            float v2 = __shfl_sync(0xffffffffu, s[ks][2], srcA, 4);
            float v3 = __shfl_sync(0xffffffffu, s[ks][3], srcA, 4);
            float w0 = __shfl_sync(0xffffffffu, s[ks][0], srcB, 4);
            float w1 = __shfl_sync(0xffffffffu, s[ks][1], srcB, 4);
            float w2 = __shfl_sync(0xffffffffu, s[ks][2], srcB, 4);
            float w3 = __shfl_sync(0xffffffffu, s[ks][3], srcB, 4);
            uint32_t a0 = f2tf32(odd ? v1 : v0);
            uint32_t a1 = f2tf32(odd ? v3 : v2);
            uint32_t a2 = f2tf32(odd ? w1 : w0);
            uint32_t a3 = f2tf32(odd ? w3 : w2);
            #pragma unroll
            for (int j = 0; j < 16; ++j) {
                uint32_t b0 = Kb[(k0 + gc) * ALDQ + 8*j + gr];
                uint32_t b1 = Kb[(k0 + gc + 4) * ALDQ + 8*j + gr];
                MMA_TF32(o[j][0], o[j][1], o[j][2], o[j][3], a0, a1, a2, a3, b0, b1);
            }
        }
        __syncthreads();   // all warps done with Kbuf[kt&1] before reissue
    }

    // ---- epilogue (write tf32-rounded attn for the Wo GEMM) ----
    float inv0 = 1.0f / l0;
    float inv1 = 1.0f / l1;
    size_t r0 = (tok0 + q0 + wq + gr) * DMODEL + h * DHD;
    size_t r1 = (tok0 + q0 + wq + gr + 8) * DMODEL + h * DHD;
    #pragma unroll
    for (int j = 0; j < 16; ++j) {
        int c = 8*j + 2*gc;
        *(float2*)(out + r0 + c) =
            make_float2(roundtf(o[j][0] * inv0), roundtf(o[j][1] * inv0));
        *(float2*)(out + r1 + c) =
            make_float2(roundtf(o[j][2] * inv1), roundtf(o[j][3] * inv1));
    }
}

// ================= host launch =================
static inline void launch_gemm(const float* A, int lda, const float* Bt,
                               const float* bias, float* C, int ldc,
                               int N, int K, int round_out)
{
    dim3 grid(N / 128, NTOK / 128);
    gemm_cp<<<grid, 256, GEMM_SMEM>>>(A, lda, Bt, bias, C, ldc, K, round_out);
}

extern "C" void kernel_launch(void* const* d_in, const int* in_sizes, int n_in,
                              void* d_out, int out_size)
{
    (void)in_sizes; (void)n_in; (void)out_size;
    const float* x   = (const float*)d_in[0];
    const float* Wd  = (const float*)d_in[1];
    const float* bd  = (const float*)d_in[2];
    const float* Wu  = (const float*)d_in[3];
    const float* bu  = (const float*)d_in[4];
    const float* Wqd = (const float*)d_in[5];
    const float* bqd = (const float*)d_in[6];
    const float* Wqu = (const float*)d_in[7];
    const float* bqu = (const float*)d_in[8];
    const float* Wqr = (const float*)d_in[9];
    const float* bqr = (const float*)d_in[10];
    const float* Wkr = (const float*)d_in[11];
    const float* bkr = (const float*)d_in[12];
    const float* Wo  = (const float*)d_in[13];
    const float* bo  = (const float*)d_in[14];
    float* out = (float*)d_out;

    float *xt, *big0, *kvup, *big2, *attn;
    float *bt0, *wuT, *bt2, *woT, *bias0, *bias2;
    cudaGetSymbolAddress((void**)&xt,    g_xt);
    cudaGetSymbolAddress((void**)&big0,  g_big0);
    cudaGetSymbolAddress((void**)&kvup,  g_kvup);
    cudaGetSymbolAddress((void**)&big2,  g_big2);
    cudaGetSymbolAddress((void**)&attn,  g_attn);
    cudaGetSymbolAddress((void**)&bt0,   g_bt0);
    cudaGetSymbolAddress((void**)&wuT,   g_wuT);
    cudaGetSymbolAddress((void**)&bt2,   g_bt2);
    cudaGetSymbolAddress((void**)&woT,   g_woT);
    cudaGetSymbolAddress((void**)&bias0, g_bias0);
    cudaGetSymbolAddress((void**)&bias2, g_bias2);

    cudaFuncSetAttribute(gemm_cp, cudaFuncAttributeMaxDynamicSharedMemorySize,
                         GEMM_SMEM);
    cudaFuncSetAttribute(gemm_dual, cudaFuncAttributeMaxDynamicSharedMemorySize,
                         GEMM_SMEM);
    cudaFuncSetAttribute(flash_mma, cudaFuncAttributeMaxDynamicSharedMemorySize,
                         FL_SMEM);

    // L0: pre-round x
    round_tf32_kernel<<<(NTOK*DMODEL/4 + 255)/256, 256>>>(x, xt, NTOK*DMODEL/4);
    // L1: fused transpose [Wd|Wqd|Wkr] -> bt0
    transpose_multi<<<dim3(N0/32, DMODEL/32), dim3(32, 8)>>>(
        Wd, DC, Wqd, DCOMP, Wkr, NH*DRP, bt0, DMODEL);
    // L2: bias0
    concat_bias3<<<(N0 + 255)/256, 256>>>(bias0, bd, DC, bqd, DCOMP, bkr, NH*DRP);
    // L3: G1 mega-GEMM  <-- PROFILED
    launch_gemm(xt, DMODEL, bt0, bias0, big0, N0, N0, DMODEL, 1);
    // L4: transpose Wu
    transpose_multi<<<dim3(DMODEL/32, DC/32), dim3(32, 8)>>>(
        Wu, DMODEL, Wu, 0, Wu, 0, wuT, DC);
    // L5: fused transpose [Wqu|Wqr] -> bt2
    transpose_multi<<<dim3(N2/32, DCOMP/32), dim3(32, 8)>>>(
        Wqu, DMODEL, Wqr, NH*DRP, Wqr, 0, bt2, DCOMP);
    // L6: bias2
    concat_bias3<<<(N2 + 255)/256, 256>>>(bias2, bqu, DMODEL, bqr, NH*DRP,
                                          bqr, 0);
    // L7: fused dual GEMM — kv_up (16 col blocks) + (q_c|q_r) (24 col blocks)
    {
        dim3 grid(DMODEL/128 + N2/128, NTOK/128);
        gemm_dual<<<grid, 256, GEMM_SMEM>>>(
            big0, N0, wuT, bu, kvup, DMODEL, DC,
            big0 + QCMP_OFF, N0, bt2, bias2, big2, N2, DCOMP,
            DMODEL/128);
    }
    // L8: fused rope (q_r in big2, k_r in big0)
    {
        int n = NTOK * NH * 32;
        rope_kernel2<<<(2*n + 255)/256, 256>>>(big2, big0, n);
    }
    // L9: transpose Wo
    transpose_multi<<<dim3(DMODEL/32, DMODEL/32), dim3(32, 8)>>>(
        Wo, DMODEL, Wo, 0, Wo, 0, woT, DMODEL);
    // L10: attention
    {
        dim3 grid(SS / 128, NH, BB);
        flash_mma<<<grid, 256, FL_SMEM>>>(big2, kvup, big0, attn);
    }
    // L11: output projection (full fp32 output)
    launch_gemm(attn, DMODEL, woT, bo, out, DMODEL, DMODEL, DMODEL, 0);
}